// round 14
// baseline (speedup 1.0000x reference)
#include <cuda_runtime.h>
#include <cuda_fp16.h>
#include <math.h>
#include <stdint.h>

// ---------------- problem constants ----------------
#define TT    2048
#define DD    4096
#define HH    16
#define DHD   256
#define DFF   16384

// ---------------- scratch (device globals; no cudaMalloc allowed) ----------------
__device__ __half g_h  [TT * DD];      // LN output
__device__ __half g_q  [TT * DD];
__device__ __half g_k  [TT * DD];
__device__ __half g_v  [TT * DD];
__device__ __half g_y  [TT * DD];      // attention output
__device__ float  g_tmp[TT * DD];
__device__ __half g_m  [TT * DFF];
// fp16 weights in NATIVE [K,N] layout (converted, not transposed)
__device__ __half g_wt [4u*4096u*4096u + 2u*4096u*16384u];

#define WQ_OFF    0u
#define WK_OFF    16777216u
#define WV_OFF    33554432u
#define WO_OFF    50331648u
#define WIN_OFF   67108864u
#define WOUT_OFF  134217728u

// ---------------- helpers ----------------
__device__ __forceinline__ uint32_t smem_u32(const void* p) {
    uint32_t r;
    asm("{ .reg .u64 t; cvta.to.shared.u64 t, %1; cvt.u32.u64 %0, t; }" : "=r"(r) : "l"(p));
    return r;
}
__device__ __forceinline__ void cpasync16(uint32_t dst, const void* src) {
    asm volatile("cp.async.cg.shared.global [%0], [%1], 16;" :: "r"(dst), "l"(src));
}
#define CP_COMMIT() asm volatile("cp.async.commit_group;" ::: "memory")

__device__ __forceinline__ void ldsm_x4(uint32_t (&r)[4], uint32_t addr) {
    asm volatile("ldmatrix.sync.aligned.m8n8.x4.shared.b16 {%0,%1,%2,%3}, [%4];"
        : "=r"(r[0]), "=r"(r[1]), "=r"(r[2]), "=r"(r[3]) : "r"(addr));
}
__device__ __forceinline__ void ldsm_x4_trans(uint32_t (&r)[4], uint32_t addr) {
    asm volatile("ldmatrix.sync.aligned.m8n8.x4.trans.shared.b16 {%0,%1,%2,%3}, [%4];"
        : "=r"(r[0]), "=r"(r[1]), "=r"(r[2]), "=r"(r[3]) : "r"(addr));
}
__device__ __forceinline__ void mma_f16(float (&d)[4], const uint32_t (&a)[4],
                                        uint32_t b0, uint32_t b1) {
    asm volatile("mma.sync.aligned.m16n8k16.row.col.f32.f16.f16.f32 "
        "{%0,%1,%2,%3}, {%4,%5,%6,%7}, {%8,%9}, {%0,%1,%2,%3};"
        : "+f"(d[0]), "+f"(d[1]), "+f"(d[2]), "+f"(d[3])
        : "r"(a[0]), "r"(a[1]), "r"(a[2]), "r"(a[3]), "r"(b0), "r"(b1));
}
__device__ __forceinline__ uint32_t h2pack(float x, float y) {
    __half2 h = __floats2half2_rn(x, y);
    return *(uint32_t*)&h;
}

// swizzles: 128B-row tiles (A) and 512B-row tiles (B)
#define TSWZ(off)   ((off) ^ (((off) >> 3) & 0x70))
#define SWZ512(off) ((off) ^ (((off) >> 5) & 0x70))

// ---------------- LayerNorm (fp16 output) ----------------
__global__ __launch_bounds__(256) void ln_kernel(const float* __restrict__ x,
                                                 const float* __restrict__ g,
                                                 const float* __restrict__ b,
                                                 __half* __restrict__ h) {
    int row = blockIdx.x;
    const float4* xr = (const float4*)(x + (size_t)row * DD);
    float s = 0.f, s2 = 0.f;
    for (int i = threadIdx.x; i < DD / 4; i += 256) {
        float4 v = xr[i];
        s  += v.x + v.y + v.z + v.w;
        s2 += v.x*v.x + v.y*v.y + v.z*v.z + v.w*v.w;
    }
    for (int o = 16; o > 0; o >>= 1) {
        s  += __shfl_xor_sync(~0u, s,  o);
        s2 += __shfl_xor_sync(~0u, s2, o);
    }
    __shared__ float sh[16];
    int w = threadIdx.x >> 5;
    if ((threadIdx.x & 31) == 0) { sh[w] = s; sh[8 + w] = s2; }
    __syncthreads();
    if (threadIdx.x < 32) {
        float a = threadIdx.x < 8 ? sh[threadIdx.x]     : 0.f;
        float c = threadIdx.x < 8 ? sh[8 + threadIdx.x] : 0.f;
        for (int o = 4; o > 0; o >>= 1) {
            a += __shfl_xor_sync(~0u, a, o);
            c += __shfl_xor_sync(~0u, c, o);
        }
        if (threadIdx.x == 0) { sh[0] = a; sh[8] = c; }
    }
    __syncthreads();
    float mean = sh[0] * (1.f / DD);
    float var  = sh[8] * (1.f / DD) - mean * mean;
    float rstd = rsqrtf(var + 1e-6f);
    __half2* hr = (__half2*)(h + (size_t)row * DD);
    const float4* gg4 = (const float4*)g;
    const float4* bb4 = (const float4*)b;
    for (int i = threadIdx.x; i < DD / 4; i += 256) {
        float4 v = xr[i], gg = gg4[i], bb = bb4[i];
        hr[i * 2]     = __floats2half2_rn((v.x - mean) * rstd * gg.x + bb.x,
                                          (v.y - mean) * rstd * gg.y + bb.y);
        hr[i * 2 + 1] = __floats2half2_rn((v.z - mean) * rstd * gg.z + bb.z,
                                          (v.w - mean) * rstd * gg.w + bb.w);
    }
}

// ---------------- streaming fp32 -> fp16 convert (layout preserved) ----------------
__global__ __launch_bounds__(256) void convert_kernel(const float4* __restrict__ in,
                                                      uint2* __restrict__ out) {
    int i = blockIdx.x * 256 + threadIdx.x;
    float4 v = in[i];
    uint2 o;
    o.x = h2pack(v.x, v.y);
    o.y = h2pack(v.z, v.w);
    out[i] = o;
}

// ---------------- RoPE in-place on fp16 q, k ----------------
__global__ __launch_bounds__(256) void rope_kernel(__half* __restrict__ q, __half* __restrict__ k) {
    int idx = blockIdx.x * 256 + threadIdx.x;
    int f = idx & 31;
    int hh = (idx >> 5) & (HH - 1);
    int t = idx >> 9;
    float inv = 1.0f / powf(10000.0f, (float)f * (1.0f / 32.0f));
    float ang = (float)t * inv;
    float sn, cs;
    sincosf(ang, &sn, &cs);
    size_t base = (size_t)t * DD + hh * DHD + f;
    {
        float a = __half2float(q[base]), b = __half2float(q[base + 32]);
        q[base]      = __float2half_rn(a * cs - b * sn);
        q[base + 32] = __float2half_rn(a * sn + b * cs);
    }
    {
        float a = __half2float(k[base]), b = __half2float(k[base + 32]);
        k[base]      = __float2half_rn(a * cs - b * sn);
        k[base + 32] = __float2half_rn(a * sn + b * cs);
    }
}

// ---------------- fp16 mma GEMM: CTA 128x256, warp 64x64, 4-stage cp.async,
// fragment double-buffered inner loop with spread cp.async issuance ----------------
__device__ __forceinline__ float gelu_f(float v) {
    float t = tanhf(0.7978845608028654f * (v + 0.044715f * v * v * v));
    return 0.5f * v * (1.f + t);
}

#define STAGE_BYTES 49152            // A 16KB (128m x 128B) + B 32KB (64k x 512B)
#define B_SMEM_OFF  16384
#define GSTAGES 4
#define GSMEM_TOTAL (GSTAGES * STAGE_BYTES)   // 196608

template <int EPI, typename OutT>
__device__ __forceinline__ void tgemm_body(const __half* __restrict__ A, const __half* __restrict__ B,
                                           const float* __restrict__ bias, const float* __restrict__ res,
                                           OutT* __restrict__ C, int N, int K) {
    extern __shared__ __align__(1024) char gsm[];
    uint32_t sbase = smem_u32(gsm);
    int tid = threadIdx.x, lane = tid & 31, wid = tid >> 5;

    // column-major CTA raster (B strip shared by co-resident CTAs)
    int bid = blockIdx.y * gridDim.x + blockIdx.x;
    int by  = bid % gridDim.y;
    int bx  = bid / gridDim.y;
    int bm = by * 128, bn = bx * 256;

    int ntiles = K >> 6;
    int wm = (wid >> 2) * 64, wn = (wid & 3) * 64;

    uint32_t doffA[4]; int soffA[4];
#pragma unroll
    for (int j = 0; j < 4; ++j) {
        int idx = tid + 256 * j;
        int row = idx >> 3, seg = idx & 7;
        soffA[j] = row * K + seg * 8;
        doffA[j] = TSWZ((uint32_t)(row * 128 + seg * 16));
    }
    uint32_t doffB[8]; size_t soffB[8];
#pragma unroll
    for (int j = 0; j < 8; ++j) {
        int idx = tid + 256 * j;
        int krow = idx >> 5, seg = idx & 31;
        soffB[j] = (size_t)krow * N + seg * 8;
        doffB[j] = B_SMEM_OFF + SWZ512((uint32_t)(krow * 512 + seg * 16));
    }
    const __half* Abase = A + (size_t)bm * K;
    const __half* Bbase = B + bn;

#pragma unroll
    for (int p = 0; p < GSTAGES - 1; ++p) {
        uint32_t stb = sbase + p * STAGE_BYTES;
#pragma unroll
        for (int j = 0; j < 4; ++j) cpasync16(stb + doffA[j], Abase + soffA[j] + p * 64);
#pragma unroll
        for (int j = 0; j < 8; ++j) cpasync16(stb + doffB[j], Bbase + soffB[j] + (size_t)p * 64 * N);
        CP_COMMIT();
    }

    float acc[4][8][4];
#pragma unroll
    for (int i = 0; i < 4; ++i)
#pragma unroll
        for (int j = 0; j < 8; ++j)
#pragma unroll
            for (int e = 0; e < 4; ++e) acc[i][j][e] = 0.f;

    int dr = ((lane >> 3) & 1) * 8 + (lane & 7);
    int dk = ((lane >> 4) & 1) * 16;
    int vmI = lane >> 3, vii = lane & 7;
    int vsrow = (vmI & 1) * 8 + vii;
    int vcolb = (vmI >> 1) * 16;

    uint32_t af[2][4][4];   // [buf][i][frag]
    uint32_t bf[2][4][4];   // [buf][jj][frag]

    int stage = 0;
    for (int kt = 0; kt < ntiles; ++kt) {
        asm volatile("cp.async.wait_group 2;" ::: "memory");
        __syncthreads();

        uint32_t stb = sbase + stage * STAGE_BYTES;
        int jt = kt + 3;
        bool pf = (jt < ntiles);
        int ps = stage + 3; if (ps >= GSTAGES) ps -= GSTAGES;
        uint32_t pstb = sbase + ps * STAGE_BYTES;

        // load fragments for k16 = 0 into buffer 0
#pragma unroll
        for (int i = 0; i < 4; ++i)
            ldsm_x4(af[0][i], stb + TSWZ((uint32_t)((wm + i * 16 + dr) * 128) + (uint32_t)dk));
#pragma unroll
        for (int jj = 0; jj < 4; ++jj) {
            uint32_t off = (uint32_t)(vsrow * 512 + (wn + jj * 16) * 2 + vcolb);
            ldsm_x4_trans(bf[0][jj], stb + B_SMEM_OFF + SWZ512(off));
        }

#pragma unroll
        for (int k16 = 0; k16 < 4; ++k16) {
            int cur = k16 & 1, nxt = cur ^ 1;
            // prefetch next k16 group's fragments (overlaps with mma below)
            if (k16 < 3) {
                uint32_t kb = (uint32_t)((k16 + 1) * 32 + dk);
#pragma unroll
                for (int i = 0; i < 4; ++i)
                    ldsm_x4(af[nxt][i], stb + TSWZ((uint32_t)((wm + i * 16 + dr) * 128) + kb));
#pragma unroll
                for (int jj = 0; jj < 4; ++jj) {
                    uint32_t off = (uint32_t)(((k16 + 1) * 16 + vsrow) * 512 + (wn + jj * 16) * 2 + vcolb);
                    ldsm_x4_trans(bf[nxt][jj], stb + B_SMEM_OFF + SWZ512(off));
                }
            }
            // spread gmem->smem prefetch for stage kt+3 across k16 groups
            if (pf) {
                if (k16 == 0) {
#pragma unroll
                    for (int j = 0; j < 4; ++j) cpasync16(pstb + doffA[j], Abase + soffA[j] + jt * 64);
                } else if (k16 == 1) {
#pragma unroll
                    for (int j = 0; j < 4; ++j) cpasync16(pstb + doffB[j], Bbase + soffB[j] + (size_t)jt * 64 * N);
                } else if (k16 == 2) {
#pragma unroll
                    for (int j = 4; j < 8; ++j) cpasync16(pstb + doffB[j], Bbase + soffB[j] + (size_t)jt * 64 * N);
                }
            }
#pragma unroll
            for (int i = 0; i < 4; ++i)
#pragma unroll
                for (int jj = 0; jj < 4; ++jj) {
                    mma_f16(acc[i][2 * jj],     af[cur][i], bf[cur][jj][0], bf[cur][jj][1]);
                    mma_f16(acc[i][2 * jj + 1], af[cur][i], bf[cur][jj][2], bf[cur][jj][3]);
                }
        }
        CP_COMMIT();
        if (++stage == GSTAGES) stage = 0;
    }

    int lr = lane >> 2, lc = (lane & 3) * 2;
#pragma unroll
    for (int i = 0; i < 4; ++i) {
        int r0 = bm + wm + i * 16 + lr;
        int r1 = r0 + 8;
        size_t ro0 = (size_t)r0 * N, ro1 = (size_t)r1 * N;
#pragma unroll
        for (int j = 0; j < 8; ++j) {
            int c = bn + wn + j * 8 + lc;
            float2 v0 = make_float2(acc[i][j][0], acc[i][j][1]);
            float2 v1 = make_float2(acc[i][j][2], acc[i][j][3]);
            if (EPI == 1) {
                float2 bb = *(const float2*)(bias + c);
                v0.x = gelu_f(v0.x + bb.x); v0.y = gelu_f(v0.y + bb.y);
                v1.x = gelu_f(v1.x + bb.x); v1.y = gelu_f(v1.y + bb.y);
            } else if (EPI == 2) {
                float2 ra = *(const float2*)(res + ro0 + c);
                float2 rb = *(const float2*)(res + ro1 + c);
                v0.x += ra.x; v0.y += ra.y; v1.x += rb.x; v1.y += rb.y;
            } else if (EPI == 3) {
                float2 bb = *(const float2*)(bias + c);
                float2 ra = *(const float2*)(res + ro0 + c);
                float2 rb = *(const float2*)(res + ro1 + c);
                v0.x += bb.x + ra.x; v0.y += bb.y + ra.y;
                v1.x += bb.x + rb.x; v1.y += bb.y + rb.y;
            }
            if (sizeof(OutT) == 2) {
                *(__half2*)((__half*)C + ro0 + c) = __floats2half2_rn(v0.x, v0.y);
                *(__half2*)((__half*)C + ro1 + c) = __floats2half2_rn(v1.x, v1.y);
            } else {
                *(float2*)((float*)C + ro0 + c) = v0;
                *(float2*)((float*)C + ro1 + c) = v1;
            }
        }
    }
}

template <int EPI, typename OutT>
__global__ __launch_bounds__(256, 1)
void tgemm_kernel(const __half* __restrict__ A, const __half* __restrict__ B,
                  const float* __restrict__ bias, const float* __restrict__ res,
                  OutT* __restrict__ C, int N, int K) {
    tgemm_body<EPI, OutT>(A, B, bias, res, C, N, K);
}

__global__ __launch_bounds__(256, 1)
void tgemm_qkv_kernel(const __half* __restrict__ h, const __half* __restrict__ wt,
                      __half* __restrict__ q, __half* __restrict__ k, __half* __restrict__ v) {
    const __half* B = (blockIdx.z == 0) ? (wt + WQ_OFF) : (blockIdx.z == 1) ? (wt + WK_OFF) : (wt + WV_OFF);
    __half* C       = (blockIdx.z == 0) ? q : (blockIdx.z == 1) ? k : v;
    tgemm_body<0, __half>(h, B, nullptr, nullptr, C, DD, DD);
}

// ---------------- fp16 mma flash attention: Br=128, 8 warps, Bc=64 ----------------
#define AT_ROWB    528
#define ATQ_BYTES  (128 * AT_ROWB)                 // 67584
#define ATKV_BYTES (64 * AT_ROWB)                  // 33792
#define ATTN_SMEM  (ATQ_BYTES + 4 * ATKV_BYTES)    // 202752

__device__ __forceinline__ void attn_load_q(uint32_t dstb, const __half* src, int tid) {
#pragma unroll
    for (int j = 0; j < 16; ++j) {
        int idx = tid + 256 * j;
        int row = idx >> 5, seg = idx & 31;
        cpasync16(dstb + row * AT_ROWB + seg * 16, src + (size_t)row * DD + seg * 8);
    }
}
__device__ __forceinline__ void attn_load_kv(uint32_t dstb, const __half* src, int tid) {
#pragma unroll
    for (int j = 0; j < 8; ++j) {
        int idx = tid + 256 * j;
        int row = idx >> 5, seg = idx & 31;
        cpasync16(dstb + row * AT_ROWB + seg * 16, src + (size_t)row * DD + seg * 8);
    }
}

__global__ __launch_bounds__(256, 1) void attn_kernel(const __half* __restrict__ q,
                                                      const __half* __restrict__ k,
                                                      const __half* __restrict__ v,
                                                      __half* __restrict__ y) {
    extern __shared__ __align__(1024) char asmem[];
    uint32_t sb = smem_u32(asmem);
    int tid = threadIdx.x, lane = tid & 31, wid = tid >> 5;   // 8 warps
    int qt = gridDim.x - 1 - blockIdx.x;                      // heavy tiles first
    int hh = blockIdx.y;
    size_t hoff = (size_t)hh * DHD;
    int ntk = 2 * qt + 2;

    uint32_t Qb = sb;
    uint32_t Kb[2] = { sb + ATQ_BYTES, sb + ATQ_BYTES + ATKV_BYTES };
    uint32_t Vb[2] = { sb + ATQ_BYTES + 2 * ATKV_BYTES, sb + ATQ_BYTES + 3 * ATKV_BYTES };

    const __half* qsrc = q + (size_t)(qt * 128) * DD + hoff;

    attn_load_q(Qb, qsrc, tid);
    attn_load_kv(Kb[0], k + hoff, tid);
    attn_load_kv(Vb[0], v + hoff, tid);
    CP_COMMIT();
    attn_load_kv(Kb[1], k + (size_t)64 * DD + hoff, tid);
    attn_load_kv(Vb[1], v + (size_t)64 * DD + hoff, tid);
    CP_COMMIT();

    float o[32][4];
#pragma unroll
    for (int j = 0; j < 32; ++j)
#pragma unroll
        for (int e = 0; e < 4; ++e) o[j][e] = 0.f;
    float m0 = -1e30f, m1 = -1e30f, l0 = 0.f, l1 = 0.f;

    int dr = ((lane >> 3) & 1) * 8 + (lane & 7);
    int dk = ((lane >> 4) & 1) * 16;
    int wm = wid * 16;                       // warp's 16 q-rows within 128
    int lr = lane >> 2, lc = (lane & 3) * 2;
    int vmI = lane >> 3, vii = lane & 7;
    int vsrow = (vmI & 1) * 8 + vii;
    int vcolb = (vmI >> 1) * 16;

    for (int kt = 0; kt < ntk; ++kt) {
        asm volatile("cp.async.wait_group 1;" ::: "memory");
        __syncthreads();
        uint32_t Kt = Kb[kt & 1], Vt = Vb[kt & 1];

        // fully-masked warp tile? (entire 16 rows above diagonal for this kt)
        bool active = (kt * 64 <= qt * 128 + wm + 15);
        if (active) {
            // ---- S = Q K^T : warp computes 16x64 ----
            float s[8][4];
#pragma unroll
            for (int j = 0; j < 8; ++j)
#pragma unroll
                for (int e = 0; e < 4; ++e) s[j][e] = 0.f;

#pragma unroll
            for (int k16 = 0; k16 < 16; ++k16) {
                uint32_t kb = (uint32_t)(k16 * 32 + dk);
                uint32_t a[4];
                ldsm_x4(a, Qb + (uint32_t)((wm + dr) * AT_ROWB) + kb);
#pragma unroll
                for (int jj = 0; jj < 4; ++jj) {
                    uint32_t b[4];
                    ldsm_x4(b, Kt + (uint32_t)((jj * 16 + dr) * AT_ROWB) + kb);
                    mma_f16(s[2 * jj],     a, b[0], b[2]);
                    mma_f16(s[2 * jj + 1], a, b[1], b[3]);
                }
            }

#pragma unroll
            for (int j = 0; j < 8; ++j)
#pragma unroll
                for (int e = 0; e < 4; ++e) s[j][e] *= 0.0625f;
            if (kt >= 2 * qt) {       // tiles intersecting the diagonal
                int rowg_base = qt * 128 + wm + lr;
                int colg_base = kt * 64 + lc;
#pragma unroll
                for (int j = 0; j < 8; ++j)
#pragma unroll
                    for (int e = 0; e < 4; ++e) {
                        int colg = colg_base + 8 * j + (e & 1);
                        int rowg = rowg_base + ((e >> 1) << 3);
                        if (colg > rowg) s[j][e] = -1e30f;
                    }
            }

            // ---- online softmax (rows lr, lr+8 of warp tile) ----
            float tm0 = -1e30f, tm1 = -1e30f;
#pragma unroll
            for (int j = 0; j < 8; ++j) {
                tm0 = fmaxf(tm0, fmaxf(s[j][0], s[j][1]));
                tm1 = fmaxf(tm1, fmaxf(s[j][2], s[j][3]));
            }
            tm0 = fmaxf(tm0, __shfl_xor_sync(~0u, tm0, 1));
            tm0 = fmaxf(tm0, __shfl_xor_sync(~0u, tm0, 2));
            tm1 = fmaxf(tm1, __shfl_xor_sync(~0u, tm1, 1));
            tm1 = fmaxf(tm1, __shfl_xor_sync(~0u, tm1, 2));
            float nm0 = fmaxf(m0, tm0), nm1 = fmaxf(m1, tm1);
            float al0 = __expf(m0 - nm0), al1 = __expf(m1 - nm1);
            m0 = nm0; m1 = nm1;
            float rs0 = 0.f, rs1 = 0.f;
#pragma unroll
            for (int j = 0; j < 8; ++j) {
                s[j][0] = __expf(s[j][0] - nm0);
                s[j][1] = __expf(s[j][1] - nm0);
                s[j][2] = __expf(s[j][2] - nm1);
                s[j][3] = __expf(s[j][3] - nm1);
                rs0 += s[j][0] + s[j][1];
                rs1 += s[j][2] + s[j][3];
            }
            rs0 += __shfl_xor_sync(~0u, rs0, 1); rs0 += __shfl_xor_sync(~0u, rs0, 2);
            rs1 += __shfl_xor_sync(~0u, rs1, 1); rs1 += __shfl_xor_sync(~0u, rs1, 2);
            l0 = l0 * al0 + rs0;
            l1 = l1 * al1 + rs1;
#pragma unroll
            for (int j = 0; j < 32; ++j) {
                o[j][0] *= al0; o[j][1] *= al0;
                o[j][2] *= al1; o[j][3] *= al1;
            }

            // ---- O += P V ----
#pragma unroll
            for (int t = 0; t < 4; ++t) {
                uint32_t pa[4];
                pa[0] = h2pack(s[2 * t][0],     s[2 * t][1]);
                pa[1] = h2pack(s[2 * t][2],     s[2 * t][3]);
                pa[2] = h2pack(s[2 * t + 1][0], s[2 * t + 1][1]);
                pa[3] = h2pack(s[2 * t + 1][2], s[2 * t + 1][3]);
                uint32_t vrow = (uint32_t)((16 * t + vsrow) * AT_ROWB);
#pragma unroll
                for (int np = 0; np < 16; ++np) {
                    uint32_t bb[4];
                    ldsm_x4_trans(bb, Vt + vrow + (uint32_t)(np * 32 + vcolb));
                    mma_f16(o[2 * np],     pa, bb[0], bb[1]);
                    mma_f16(o[2 * np + 1], pa, bb[2], bb[3]);
                }
            }
        }

        __syncthreads();
        int jt = kt + 2;
        if (jt < ntk) {
            attn_load_kv(Kb[kt & 1], k + (size_t)(jt * 64) * DD + hoff, tid);
            attn_load_kv(Vb[kt & 1], v + (size_t)(jt * 64) * DD + hoff, tid);
        }
        CP_COMMIT();
    }

    float inv0 = 1.f / l0, inv1 = 1.f / l1;
    size_t r0 = (size_t)(qt * 128 + wm + lr) * DD + hoff;
    size_t r1 = r0 + (size_t)8 * DD;
#pragma unroll
    for (int j = 0; j < 32; ++j) {
        *(__half2*)(y + r0 + 8 * j + lc) = __floats2half2_rn(o[j][0] * inv0, o[j][1] * inv0);
        *(__half2*)(y + r1 + 8 * j + lc) = __floats2half2_rn(o[j][2] * inv1, o[j][3] * inv1);
    }
}

// ---------------- launcher (tri-stream overlap) ----------------
extern "C" void kernel_launch(void* const* d_in, const int* in_sizes, int n_in,
                              void* d_out, int out_size) {
    const float* x     = (const float*)d_in[0];
    const float* wq    = (const float*)d_in[1];
    const float* wk    = (const float*)d_in[2];
    const float* wv    = (const float*)d_in[3];
    const float* wo    = (const float*)d_in[4];
    const float* w_in  = (const float*)d_in[5];
    const float* b_in  = (const float*)d_in[6];
    const float* w_out = (const float*)d_in[7];
    const float* b_out = (const float*)d_in[8];
    const float* ln_s  = (const float*)d_in[9];
    const float* ln_o  = (const float*)d_in[10];
    float* out = (float*)d_out;

    __half *h, *q, *k, *v, *y, *m, *wt;
    float *tmp;
    cudaGetSymbolAddress((void**)&h,   g_h);
    cudaGetSymbolAddress((void**)&q,   g_q);
    cudaGetSymbolAddress((void**)&k,   g_k);
    cudaGetSymbolAddress((void**)&v,   g_v);
    cudaGetSymbolAddress((void**)&y,   g_y);
    cudaGetSymbolAddress((void**)&tmp, g_tmp);
    cudaGetSymbolAddress((void**)&m,   g_m);
    cudaGetSymbolAddress((void**)&wt,  g_wt);

    cudaFuncSetAttribute(attn_kernel, cudaFuncAttributeMaxDynamicSharedMemorySize, ATTN_SMEM);
    cudaFuncSetAttribute(tgemm_qkv_kernel, cudaFuncAttributeMaxDynamicSharedMemorySize, GSMEM_TOTAL);
    cudaFuncSetAttribute(tgemm_kernel<1, __half>, cudaFuncAttributeMaxDynamicSharedMemorySize, GSMEM_TOTAL);
    cudaFuncSetAttribute(tgemm_kernel<2, float>,  cudaFuncAttributeMaxDynamicSharedMemorySize, GSMEM_TOTAL);
    cudaFuncSetAttribute(tgemm_kernel<3, float>,  cudaFuncAttributeMaxDynamicSharedMemorySize, GSMEM_TOTAL);

    // lazy one-time stream/event setup (handles only; no device allocations)
    static cudaStream_t s1 = nullptr, s2 = nullptr;
    static cudaEvent_t evRoot = nullptr, evLN = nullptr, evKV = nullptr,
                       evWoCv = nullptr, evWoutCv = nullptr, evM = nullptr;
    if (s1 == nullptr) {
        cudaStreamCreateWithFlags(&s1, cudaStreamNonBlocking);
        cudaStreamCreateWithFlags(&s2, cudaStreamNonBlocking);
        cudaEventCreateWithFlags(&evRoot,   cudaEventDisableTiming);
        cudaEventCreateWithFlags(&evLN,     cudaEventDisableTiming);
        cudaEventCreateWithFlags(&evKV,     cudaEventDisableTiming);
        cudaEventCreateWithFlags(&evWoCv,   cudaEventDisableTiming);
        cudaEventCreateWithFlags(&evWoutCv, cudaEventDisableTiming);
        cudaEventCreateWithFlags(&evM,      cudaEventDisableTiming);
    }

    const int G44  = (DD / 4) * DD / 256;
    const int G416 = (DD / 4) * DFF / 256;

    // fork s1, s2 from main stream
    cudaEventRecord(evRoot, 0);
    cudaStreamWaitEvent(s1, evRoot, 0);
    cudaStreamWaitEvent(s2, evRoot, 0);

    // s2: wo + w_out converts (consumed late; hide under GEMMs)
    convert_kernel<<<G44, 256, 0, s2>>>((const float4*)wo, (uint2*)(wt + WO_OFF));
    cudaEventRecord(evWoCv, s2);
    convert_kernel<<<G416, 256, 0, s2>>>((const float4*)w_out, (uint2*)(wt + WOUT_OFF));
    cudaEventRecord(evWoutCv, s2);

    // s1: wk + wv converts (QKV dep), then w_in convert + MLP-in GEMM
    convert_kernel<<<G44, 256, 0, s1>>>((const float4*)wk, (uint2*)(wt + WK_OFF));
    convert_kernel<<<G44, 256, 0, s1>>>((const float4*)wv, (uint2*)(wt + WV_OFF));
    cudaEventRecord(evKV, s1);
    convert_kernel<<<G416, 256, 0, s1>>>((const float4*)w_in, (uint2*)(wt + WIN_OFF));

    // main: wq convert + LN
    convert_kernel<<<G44, 256>>>((const float4*)wq, (uint2*)(wt + WQ_OFF));
    ln_kernel<<<TT, 256>>>(x, ln_s, ln_o, h);
    cudaEventRecord(evLN, 0);

    // s1: MLP-in GEMM (needs h + w_in)
    cudaStreamWaitEvent(s1, evLN, 0);
    tgemm_kernel<1, __half><<<dim3(DFF / 256, TT / 128), 256, GSMEM_TOTAL, s1>>>(h, wt + WIN_OFF, b_in, nullptr, m, DFF, DD);
    cudaEventRecord(evM, s1);

    // main: QKV -> RoPE -> attention -> Wo
    cudaStreamWaitEvent(0, evKV, 0);
    tgemm_qkv_kernel<<<dim3(DD / 256, TT / 128, 3), 256, GSMEM_TOTAL>>>(h, wt, q, k, v);
    rope_kernel<<<(TT * HH * 32) / 256, 256>>>(q, k);
    attn_kernel<<<dim3(TT / 128, HH), 256, ATTN_SMEM>>>(q, k, v, y);
    cudaStreamWaitEvent(0, evWoCv, 0);
    tgemm_kernel<2, float><<<dim3(DD / 256, TT / 128), 256, GSMEM_TOTAL>>>(y, wt + WO_OFF, nullptr, x, tmp, DD, DD);

    // join: MLP-out needs m (s1), w_out (s2), tmp (main)
    cudaStreamWaitEvent(0, evM, 0);
    cudaStreamWaitEvent(0, evWoutCv, 0);
    tgemm_kernel<3, float><<<dim3(DD / 256, TT / 128), 256, GSMEM_TOTAL>>>(m, wt + WOUT_OFF, b_out, tmp, out, DD, DFF);
}

// round 15
// speedup vs baseline: 1.1646x; 1.1646x over previous
#include <cuda_runtime.h>
#include <cuda_fp16.h>
#include <math.h>
#include <stdint.h>

// ---------------- problem constants ----------------
#define TT    2048
#define DD    4096
#define HH    16
#define DHD   256
#define DFF   16384

// ---------------- scratch (device globals; no cudaMalloc allowed) ----------------
__device__ __half g_h  [TT * DD];      // LN output
__device__ __half g_q  [TT * DD];
__device__ __half g_k  [TT * DD];
__device__ __half g_v  [TT * DD];
__device__ __half g_y  [TT * DD];      // attention output
__device__ float  g_tmp[TT * DD];
__device__ __half g_m  [TT * DFF];
// fp16 weights in NATIVE [K,N] layout (converted, not transposed)
__device__ __half g_wt [4u*4096u*4096u + 2u*4096u*16384u];

#define WQ_OFF    0u
#define WK_OFF    16777216u
#define WV_OFF    33554432u
#define WO_OFF    50331648u
#define WIN_OFF   67108864u
#define WOUT_OFF  134217728u

// ---------------- helpers ----------------
__device__ __forceinline__ uint32_t smem_u32(const void* p) {
    uint32_t r;
    asm("{ .reg .u64 t; cvta.to.shared.u64 t, %1; cvt.u32.u64 %0, t; }" : "=r"(r) : "l"(p));
    return r;
}
__device__ __forceinline__ void cpasync16(uint32_t dst, const void* src) {
    asm volatile("cp.async.cg.shared.global [%0], [%1], 16;" :: "r"(dst), "l"(src));
}
#define CP_COMMIT() asm volatile("cp.async.commit_group;" ::: "memory")

__device__ __forceinline__ void ldsm_x4(uint32_t (&r)[4], uint32_t addr) {
    asm volatile("ldmatrix.sync.aligned.m8n8.x4.shared.b16 {%0,%1,%2,%3}, [%4];"
        : "=r"(r[0]), "=r"(r[1]), "=r"(r[2]), "=r"(r[3]) : "r"(addr));
}
__device__ __forceinline__ void ldsm_x4_trans(uint32_t (&r)[4], uint32_t addr) {
    asm volatile("ldmatrix.sync.aligned.m8n8.x4.trans.shared.b16 {%0,%1,%2,%3}, [%4];"
        : "=r"(r[0]), "=r"(r[1]), "=r"(r[2]), "=r"(r[3]) : "r"(addr));
}
__device__ __forceinline__ void mma_f16(float (&d)[4], const uint32_t (&a)[4],
                                        uint32_t b0, uint32_t b1) {
    asm volatile("mma.sync.aligned.m16n8k16.row.col.f32.f16.f16.f32 "
        "{%0,%1,%2,%3}, {%4,%5,%6,%7}, {%8,%9}, {%0,%1,%2,%3};"
        : "+f"(d[0]), "+f"(d[1]), "+f"(d[2]), "+f"(d[3])
        : "r"(a[0]), "r"(a[1]), "r"(a[2]), "r"(a[3]), "r"(b0), "r"(b1));
}
__device__ __forceinline__ uint32_t h2pack(float x, float y) {
    __half2 h = __floats2half2_rn(x, y);
    return *(uint32_t*)&h;
}

// swizzles: 128B-row tiles (A) and 512B-row tiles (B)
#define TSWZ(off)   ((off) ^ (((off) >> 3) & 0x70))
#define SWZ512(off) ((off) ^ (((off) >> 5) & 0x70))

// ---------------- LayerNorm (fp16 output) ----------------
__global__ __launch_bounds__(256) void ln_kernel(const float* __restrict__ x,
                                                 const float* __restrict__ g,
                                                 const float* __restrict__ b,
                                                 __half* __restrict__ h) {
    int row = blockIdx.x;
    const float4* xr = (const float4*)(x + (size_t)row * DD);
    float s = 0.f, s2 = 0.f;
    for (int i = threadIdx.x; i < DD / 4; i += 256) {
        float4 v = xr[i];
        s  += v.x + v.y + v.z + v.w;
        s2 += v.x*v.x + v.y*v.y + v.z*v.z + v.w*v.w;
    }
    for (int o = 16; o > 0; o >>= 1) {
        s  += __shfl_xor_sync(~0u, s,  o);
        s2 += __shfl_xor_sync(~0u, s2, o);
    }
    __shared__ float sh[16];
    int w = threadIdx.x >> 5;
    if ((threadIdx.x & 31) == 0) { sh[w] = s; sh[8 + w] = s2; }
    __syncthreads();
    if (threadIdx.x < 32) {
        float a = threadIdx.x < 8 ? sh[threadIdx.x]     : 0.f;
        float c = threadIdx.x < 8 ? sh[8 + threadIdx.x] : 0.f;
        for (int o = 4; o > 0; o >>= 1) {
            a += __shfl_xor_sync(~0u, a, o);
            c += __shfl_xor_sync(~0u, c, o);
        }
        if (threadIdx.x == 0) { sh[0] = a; sh[8] = c; }
    }
    __syncthreads();
    float mean = sh[0] * (1.f / DD);
    float var  = sh[8] * (1.f / DD) - mean * mean;
    float rstd = rsqrtf(var + 1e-6f);
    __half2* hr = (__half2*)(h + (size_t)row * DD);
    const float4* gg4 = (const float4*)g;
    const float4* bb4 = (const float4*)b;
    for (int i = threadIdx.x; i < DD / 4; i += 256) {
        float4 v = xr[i], gg = gg4[i], bb = bb4[i];
        hr[i * 2]     = __floats2half2_rn((v.x - mean) * rstd * gg.x + bb.x,
                                          (v.y - mean) * rstd * gg.y + bb.y);
        hr[i * 2 + 1] = __floats2half2_rn((v.z - mean) * rstd * gg.z + bb.z,
                                          (v.w - mean) * rstd * gg.w + bb.w);
    }
}

// ---------------- streaming fp32 -> fp16 convert (layout preserved) ----------------
__global__ __launch_bounds__(256) void convert_kernel(const float4* __restrict__ in,
                                                      uint2* __restrict__ out) {
    int i = blockIdx.x * 256 + threadIdx.x;
    float4 v = in[i];
    uint2 o;
    o.x = h2pack(v.x, v.y);
    o.y = h2pack(v.z, v.w);
    out[i] = o;
}

// ---------------- fp16 mma GEMM: CTA 128x256, warp 64x64, 4-stage cp.async ----------------
__device__ __forceinline__ float gelu_f(float v) {
    float t = tanhf(0.7978845608028654f * (v + 0.044715f * v * v * v));
    return 0.5f * v * (1.f + t);
}

#define STAGE_BYTES 49152            // A 16KB (128m x 128B) + B 32KB (64k x 512B)
#define B_SMEM_OFF  16384
#define GSTAGES 4
#define GSMEM_TOTAL (GSTAGES * STAGE_BYTES)   // 196608

// EPI: 0 = store, 1 = gelu(acc+bias), 2 = acc+res, 3 = acc+bias+res
// ROPE_EN: compile-time; doRope: runtime (q/k outputs only). Rotation pairs
// (f, f+32) of each 256-wide head live in warp wn==0, held by the SAME thread
// at acc[., j] / acc[., j+4] — pure register transform before the store.
template <int EPI, typename OutT, bool ROPE_EN>
__device__ __forceinline__ void tgemm_body(const __half* __restrict__ A, const __half* __restrict__ B,
                                           const float* __restrict__ bias, const float* __restrict__ res,
                                           OutT* __restrict__ C, int N, int K, bool doRope) {
    extern __shared__ __align__(1024) char gsm[];
    uint32_t sbase = smem_u32(gsm);
    int tid = threadIdx.x, lane = tid & 31, wid = tid >> 5;

    // column-major CTA raster (B strip shared by co-resident CTAs)
    int bid = blockIdx.y * gridDim.x + blockIdx.x;
    int by  = bid % gridDim.y;
    int bx  = bid / gridDim.y;
    int bm = by * 128, bn = bx * 256;

    int ntiles = K >> 6;
    int wm = (wid >> 2) * 64, wn = (wid & 3) * 64;

    uint32_t doffA[4]; int soffA[4];
#pragma unroll
    for (int j = 0; j < 4; ++j) {
        int idx = tid + 256 * j;
        int row = idx >> 3, seg = idx & 7;
        soffA[j] = row * K + seg * 8;
        doffA[j] = TSWZ((uint32_t)(row * 128 + seg * 16));
    }
    uint32_t doffB[8]; size_t soffB[8];
#pragma unroll
    for (int j = 0; j < 8; ++j) {
        int idx = tid + 256 * j;
        int krow = idx >> 5, seg = idx & 31;
        soffB[j] = (size_t)krow * N + seg * 8;
        doffB[j] = B_SMEM_OFF + SWZ512((uint32_t)(krow * 512 + seg * 16));
    }
    const __half* Abase = A + (size_t)bm * K;
    const __half* Bbase = B + bn;

#pragma unroll
    for (int p = 0; p < GSTAGES - 1; ++p) {
        uint32_t stb = sbase + p * STAGE_BYTES;
#pragma unroll
        for (int j = 0; j < 4; ++j) cpasync16(stb + doffA[j], Abase + soffA[j] + p * 64);
#pragma unroll
        for (int j = 0; j < 8; ++j) cpasync16(stb + doffB[j], Bbase + soffB[j] + (size_t)p * 64 * N);
        CP_COMMIT();
    }

    float acc[4][8][4];
#pragma unroll
    for (int i = 0; i < 4; ++i)
#pragma unroll
        for (int j = 0; j < 8; ++j)
#pragma unroll
            for (int e = 0; e < 4; ++e) acc[i][j][e] = 0.f;

    int dr = ((lane >> 3) & 1) * 8 + (lane & 7);
    int dk = ((lane >> 4) & 1) * 16;
    int vmI = lane >> 3, vii = lane & 7;
    int vsrow = (vmI & 1) * 8 + vii;
    int vcolb = (vmI >> 1) * 16;

    int stage = 0;
    for (int kt = 0; kt < ntiles; ++kt) {
        asm volatile("cp.async.wait_group 2;" ::: "memory");
        __syncthreads();

        int jt = kt + 3;
        if (jt < ntiles) {
            int ps = stage + 3; if (ps >= GSTAGES) ps -= GSTAGES;
            uint32_t stb = sbase + ps * STAGE_BYTES;
#pragma unroll
            for (int j = 0; j < 4; ++j) cpasync16(stb + doffA[j], Abase + soffA[j] + jt * 64);
#pragma unroll
            for (int j = 0; j < 8; ++j) cpasync16(stb + doffB[j], Bbase + soffB[j] + (size_t)jt * 64 * N);
        }
        CP_COMMIT();

        uint32_t stb = sbase + stage * STAGE_BYTES;
#pragma unroll
        for (int k16 = 0; k16 < 4; ++k16) {
            uint32_t a[4][4];
#pragma unroll
            for (int i = 0; i < 4; ++i)
                ldsm_x4(a[i], stb + TSWZ((uint32_t)((wm + i * 16 + dr) * 128) + (uint32_t)(k16 * 32 + dk)));
            uint32_t b[4][4];
#pragma unroll
            for (int jj = 0; jj < 4; ++jj) {
                uint32_t off = (uint32_t)((k16 * 16 + vsrow) * 512 + (wn + jj * 16) * 2 + vcolb);
                ldsm_x4_trans(b[jj], stb + B_SMEM_OFF + SWZ512(off));
            }
#pragma unroll
            for (int i = 0; i < 4; ++i)
#pragma unroll
                for (int jj = 0; jj < 4; ++jj) {
                    mma_f16(acc[i][2 * jj],     a[i], b[jj][0], b[jj][1]);
                    mma_f16(acc[i][2 * jj + 1], a[i], b[jj][2], b[jj][3]);
                }
        }
        if (++stage == GSTAGES) stage = 0;
    }

    int lr = lane >> 2, lc = (lane & 3) * 2;

    // fused RoPE on q/k outputs: warp wn==0 holds head-rel cols 0..63;
    // pair (f, f+32) = (acc[.][j], acc[.][j+4]), rows r0 (e0,e1) and r0+8 (e2,e3)
    if (ROPE_EN) {
        if (doRope && wn == 0) {
            float invf[4][2];
#pragma unroll
            for (int j = 0; j < 4; ++j)
#pragma unroll
                for (int e2 = 0; e2 < 2; ++e2) {
                    int f = j * 8 + lc + e2;
                    invf[j][e2] = 1.0f / powf(10000.0f, (float)f * (1.0f / 32.0f));
                }
#pragma unroll
            for (int i = 0; i < 4; ++i) {
                int t0 = bm + wm + i * 16 + lr;
#pragma unroll
                for (int j = 0; j < 4; ++j)
#pragma unroll
                    for (int e2 = 0; e2 < 2; ++e2) {
                        float inv = invf[j][e2];
                        float sn0, cs0, sn1, cs1;
                        sincosf((float)t0 * inv, &sn0, &cs0);
                        sincosf((float)(t0 + 8) * inv, &sn1, &cs1);
                        float a0 = acc[i][j][e2],     b0 = acc[i][j + 4][e2];
                        acc[i][j][e2]       = a0 * cs0 - b0 * sn0;
                        acc[i][j + 4][e2]   = a0 * sn0 + b0 * cs0;
                        float a1 = acc[i][j][e2 + 2], b1 = acc[i][j + 4][e2 + 2];
                        acc[i][j][e2 + 2]     = a1 * cs1 - b1 * sn1;
                        acc[i][j + 4][e2 + 2] = a1 * sn1 + b1 * cs1;
                    }
            }
        }
    }

#pragma unroll
    for (int i = 0; i < 4; ++i) {
        int r0 = bm + wm + i * 16 + lr;
        int r1 = r0 + 8;
        size_t ro0 = (size_t)r0 * N, ro1 = (size_t)r1 * N;
#pragma unroll
        for (int j = 0; j < 8; ++j) {
            int c = bn + wn + j * 8 + lc;
            float2 v0 = make_float2(acc[i][j][0], acc[i][j][1]);
            float2 v1 = make_float2(acc[i][j][2], acc[i][j][3]);
            if (EPI == 1) {
                float2 bb = *(const float2*)(bias + c);
                v0.x = gelu_f(v0.x + bb.x); v0.y = gelu_f(v0.y + bb.y);
                v1.x = gelu_f(v1.x + bb.x); v1.y = gelu_f(v1.y + bb.y);
            } else if (EPI == 2) {
                float2 ra = *(const float2*)(res + ro0 + c);
                float2 rb = *(const float2*)(res + ro1 + c);
                v0.x += ra.x; v0.y += ra.y; v1.x += rb.x; v1.y += rb.y;
            } else if (EPI == 3) {
                float2 bb = *(const float2*)(bias + c);
                float2 ra = *(const float2*)(res + ro0 + c);
                float2 rb = *(const float2*)(res + ro1 + c);
                v0.x += bb.x + ra.x; v0.y += bb.y + ra.y;
                v1.x += bb.x + rb.x; v1.y += bb.y + rb.y;
            }
            if (sizeof(OutT) == 2) {
                *(__half2*)((__half*)C + ro0 + c) = __floats2half2_rn(v0.x, v0.y);
                *(__half2*)((__half*)C + ro1 + c) = __floats2half2_rn(v1.x, v1.y);
            } else {
                *(float2*)((float*)C + ro0 + c) = v0;
                *(float2*)((float*)C + ro1 + c) = v1;
            }
        }
    }
}

template <int EPI, typename OutT>
__global__ __launch_bounds__(256, 1)
void tgemm_kernel(const __half* __restrict__ A, const __half* __restrict__ B,
                  const float* __restrict__ bias, const float* __restrict__ res,
                  OutT* __restrict__ C, int N, int K) {
    tgemm_body<EPI, OutT, false>(A, B, bias, res, C, N, K, false);
}

__global__ __launch_bounds__(256, 1)
void tgemm_qkv_kernel(const __half* __restrict__ h, const __half* __restrict__ wt,
                      __half* __restrict__ q, __half* __restrict__ k, __half* __restrict__ v) {
    const __half* B = (blockIdx.z == 0) ? (wt + WQ_OFF) : (blockIdx.z == 1) ? (wt + WK_OFF) : (wt + WV_OFF);
    __half* C       = (blockIdx.z == 0) ? q : (blockIdx.z == 1) ? k : v;
    tgemm_body<0, __half, true>(h, B, nullptr, nullptr, C, DD, DD, blockIdx.z < 2);
}

// ---------------- fp16 mma flash attention: Br=128, 8 warps, Bc=64 ----------------
#define AT_ROWB    528
#define ATQ_BYTES  (128 * AT_ROWB)                 // 67584
#define ATKV_BYTES (64 * AT_ROWB)                  // 33792
#define ATTN_SMEM  (ATQ_BYTES + 4 * ATKV_BYTES)    // 202752

__device__ __forceinline__ void attn_load_q(uint32_t dstb, const __half* src, int tid) {
#pragma unroll
    for (int j = 0; j < 16; ++j) {
        int idx = tid + 256 * j;
        int row = idx >> 5, seg = idx & 31;
        cpasync16(dstb + row * AT_ROWB + seg * 16, src + (size_t)row * DD + seg * 8);
    }
}
__device__ __forceinline__ void attn_load_kv(uint32_t dstb, const __half* src, int tid) {
#pragma unroll
    for (int j = 0; j < 8; ++j) {
        int idx = tid + 256 * j;
        int row = idx >> 5, seg = idx & 31;
        cpasync16(dstb + row * AT_ROWB + seg * 16, src + (size_t)row * DD + seg * 8);
    }
}

__global__ __launch_bounds__(256, 1) void attn_kernel(const __half* __restrict__ q,
                                                      const __half* __restrict__ k,
                                                      const __half* __restrict__ v,
                                                      __half* __restrict__ y) {
    extern __shared__ __align__(1024) char asmem[];
    uint32_t sb = smem_u32(asmem);
    int tid = threadIdx.x, lane = tid & 31, wid = tid >> 5;   // 8 warps
    int qt = gridDim.x - 1 - blockIdx.x;                      // heavy tiles first
    int hh = blockIdx.y;
    size_t hoff = (size_t)hh * DHD;
    int ntk = 2 * qt + 2;

    uint32_t Qb = sb;
    uint32_t Kb[2] = { sb + ATQ_BYTES, sb + ATQ_BYTES + ATKV_BYTES };
    uint32_t Vb[2] = { sb + ATQ_BYTES + 2 * ATKV_BYTES, sb + ATQ_BYTES + 3 * ATKV_BYTES };

    const __half* qsrc = q + (size_t)(qt * 128) * DD + hoff;

    attn_load_q(Qb, qsrc, tid);
    attn_load_kv(Kb[0], k + hoff, tid);
    attn_load_kv(Vb[0], v + hoff, tid);
    CP_COMMIT();
    attn_load_kv(Kb[1], k + (size_t)64 * DD + hoff, tid);
    attn_load_kv(Vb[1], v + (size_t)64 * DD + hoff, tid);
    CP_COMMIT();

    float o[32][4];
#pragma unroll
    for (int j = 0; j < 32; ++j)
#pragma unroll
        for (int e = 0; e < 4; ++e) o[j][e] = 0.f;
    float m0 = -1e30f, m1 = -1e30f, l0 = 0.f, l1 = 0.f;

    int dr = ((lane >> 3) & 1) * 8 + (lane & 7);
    int dk = ((lane >> 4) & 1) * 16;
    int wm = wid * 16;                       // warp's 16 q-rows within 128
    int lr = lane >> 2, lc = (lane & 3) * 2;
    int vmI = lane >> 3, vii = lane & 7;
    int vsrow = (vmI & 1) * 8 + vii;
    int vcolb = (vmI >> 1) * 16;

    for (int kt = 0; kt < ntk; ++kt) {
        asm volatile("cp.async.wait_group 1;" ::: "memory");
        __syncthreads();
        uint32_t Kt = Kb[kt & 1], Vt = Vb[kt & 1];

        // fully-masked warp tile? (entire 16 rows above diagonal for this kt)
        bool active = (kt * 64 <= qt * 128 + wm + 15);
        if (active) {
            // ---- S = Q K^T : warp computes 16x64 ----
            float s[8][4];
#pragma unroll
            for (int j = 0; j < 8; ++j)
#pragma unroll
                for (int e = 0; e < 4; ++e) s[j][e] = 0.f;

#pragma unroll
            for (int k16 = 0; k16 < 16; ++k16) {
                uint32_t kb = (uint32_t)(k16 * 32 + dk);
                uint32_t a[4];
                ldsm_x4(a, Qb + (uint32_t)((wm + dr) * AT_ROWB) + kb);
#pragma unroll
                for (int jj = 0; jj < 4; ++jj) {
                    uint32_t b[4];
                    ldsm_x4(b, Kt + (uint32_t)((jj * 16 + dr) * AT_ROWB) + kb);
                    mma_f16(s[2 * jj],     a, b[0], b[2]);
                    mma_f16(s[2 * jj + 1], a, b[1], b[3]);
                }
            }

#pragma unroll
            for (int j = 0; j < 8; ++j)
#pragma unroll
                for (int e = 0; e < 4; ++e) s[j][e] *= 0.0625f;
            if (kt >= 2 * qt) {       // tiles intersecting the diagonal
                int rowg_base = qt * 128 + wm + lr;
                int colg_base = kt * 64 + lc;
#pragma unroll
                for (int j = 0; j < 8; ++j)
#pragma unroll
                    for (int e = 0; e < 4; ++e) {
                        int colg = colg_base + 8 * j + (e & 1);
                        int rowg = rowg_base + ((e >> 1) << 3);
                        if (colg > rowg) s[j][e] = -1e30f;
                    }
            }

            // ---- online softmax (rows lr, lr+8 of warp tile) ----
            float tm0 = -1e30f, tm1 = -1e30f;
#pragma unroll
            for (int j = 0; j < 8; ++j) {
                tm0 = fmaxf(tm0, fmaxf(s[j][0], s[j][1]));
                tm1 = fmaxf(tm1, fmaxf(s[j][2], s[j][3]));
            }
            tm0 = fmaxf(tm0, __shfl_xor_sync(~0u, tm0, 1));
            tm0 = fmaxf(tm0, __shfl_xor_sync(~0u, tm0, 2));
            tm1 = fmaxf(tm1, __shfl_xor_sync(~0u, tm1, 1));
            tm1 = fmaxf(tm1, __shfl_xor_sync(~0u, tm1, 2));
            float nm0 = fmaxf(m0, tm0), nm1 = fmaxf(m1, tm1);
            float al0 = __expf(m0 - nm0), al1 = __expf(m1 - nm1);
            m0 = nm0; m1 = nm1;
            float rs0 = 0.f, rs1 = 0.f;
#pragma unroll
            for (int j = 0; j < 8; ++j) {
                s[j][0] = __expf(s[j][0] - nm0);
                s[j][1] = __expf(s[j][1] - nm0);
                s[j][2] = __expf(s[j][2] - nm1);
                s[j][3] = __expf(s[j][3] - nm1);
                rs0 += s[j][0] + s[j][1];
                rs1 += s[j][2] + s[j][3];
            }
            rs0 += __shfl_xor_sync(~0u, rs0, 1); rs0 += __shfl_xor_sync(~0u, rs0, 2);
            rs1 += __shfl_xor_sync(~0u, rs1, 1); rs1 += __shfl_xor_sync(~0u, rs1, 2);
            l0 = l0 * al0 + rs0;
            l1 = l1 * al1 + rs1;
#pragma unroll
            for (int j = 0; j < 32; ++j) {
                o[j][0] *= al0; o[j][1] *= al0;
                o[j][2] *= al1; o[j][3] *= al1;
            }

            // ---- O += P V ----
#pragma unroll
            for (int t = 0; t < 4; ++t) {
                uint32_t pa[4];
                pa[0] = h2pack(s[2 * t][0],     s[2 * t][1]);
                pa[1] = h2pack(s[2 * t][2],     s[2 * t][3]);
                pa[2] = h2pack(s[2 * t + 1][0], s[2 * t + 1][1]);
                pa[3] = h2pack(s[2 * t + 1][2], s[2 * t + 1][3]);
                uint32_t vrow = (uint32_t)((16 * t + vsrow) * AT_ROWB);
#pragma unroll
                for (int np = 0; np < 16; ++np) {
                    uint32_t bb[4];
                    ldsm_x4_trans(bb, Vt + vrow + (uint32_t)(np * 32 + vcolb));
                    mma_f16(o[2 * np],     pa, bb[0], bb[1]);
                    mma_f16(o[2 * np + 1], pa, bb[2], bb[3]);
                }
            }
        }

        __syncthreads();
        int jt = kt + 2;
        if (jt < ntk) {
            attn_load_kv(Kb[kt & 1], k + (size_t)(jt * 64) * DD + hoff, tid);
            attn_load_kv(Vb[kt & 1], v + (size_t)(jt * 64) * DD + hoff, tid);
        }
        CP_COMMIT();
    }

    float inv0 = 1.f / l0, inv1 = 1.f / l1;
    size_t r0 = (size_t)(qt * 128 + wm + lr) * DD + hoff;
    size_t r1 = r0 + (size_t)8 * DD;
#pragma unroll
    for (int j = 0; j < 32; ++j) {
        *(__half2*)(y + r0 + 8 * j + lc) = __floats2half2_rn(o[j][0] * inv0, o[j][1] * inv0);
        *(__half2*)(y + r1 + 8 * j + lc) = __floats2half2_rn(o[j][2] * inv1, o[j][3] * inv1);
    }
}

// ---------------- launcher (tri-stream overlap) ----------------
extern "C" void kernel_launch(void* const* d_in, const int* in_sizes, int n_in,
                              void* d_out, int out_size) {
    const float* x     = (const float*)d_in[0];
    const float* wq    = (const float*)d_in[1];
    const float* wk    = (const float*)d_in[2];
    const float* wv    = (const float*)d_in[3];
    const float* wo    = (const float*)d_in[4];
    const float* w_in  = (const float*)d_in[5];
    const float* b_in  = (const float*)d_in[6];
    const float* w_out = (const float*)d_in[7];
    const float* b_out = (const float*)d_in[8];
    const float* ln_s  = (const float*)d_in[9];
    const float* ln_o  = (const float*)d_in[10];
    float* out = (float*)d_out;

    __half *h, *q, *k, *v, *y, *m, *wt;
    float *tmp;
    cudaGetSymbolAddress((void**)&h,   g_h);
    cudaGetSymbolAddress((void**)&q,   g_q);
    cudaGetSymbolAddress((void**)&k,   g_k);
    cudaGetSymbolAddress((void**)&v,   g_v);
    cudaGetSymbolAddress((void**)&y,   g_y);
    cudaGetSymbolAddress((void**)&tmp, g_tmp);
    cudaGetSymbolAddress((void**)&m,   g_m);
    cudaGetSymbolAddress((void**)&wt,  g_wt);

    cudaFuncSetAttribute(attn_kernel, cudaFuncAttributeMaxDynamicSharedMemorySize, ATTN_SMEM);
    cudaFuncSetAttribute(tgemm_qkv_kernel, cudaFuncAttributeMaxDynamicSharedMemorySize, GSMEM_TOTAL);
    cudaFuncSetAttribute(tgemm_kernel<1, __half>, cudaFuncAttributeMaxDynamicSharedMemorySize, GSMEM_TOTAL);
    cudaFuncSetAttribute(tgemm_kernel<2, float>,  cudaFuncAttributeMaxDynamicSharedMemorySize, GSMEM_TOTAL);
    cudaFuncSetAttribute(tgemm_kernel<3, float>,  cudaFuncAttributeMaxDynamicSharedMemorySize, GSMEM_TOTAL);

    // lazy one-time stream/event setup (handles only; no device allocations)
    static cudaStream_t s1 = nullptr, s2 = nullptr;
    static cudaEvent_t evRoot = nullptr, evLN = nullptr, evKV = nullptr,
                       evWoCv = nullptr, evWoutCv = nullptr, evM = nullptr;
    if (s1 == nullptr) {
        cudaStreamCreateWithFlags(&s1, cudaStreamNonBlocking);
        cudaStreamCreateWithFlags(&s2, cudaStreamNonBlocking);
        cudaEventCreateWithFlags(&evRoot,   cudaEventDisableTiming);
        cudaEventCreateWithFlags(&evLN,     cudaEventDisableTiming);
        cudaEventCreateWithFlags(&evKV,     cudaEventDisableTiming);
        cudaEventCreateWithFlags(&evWoCv,   cudaEventDisableTiming);
        cudaEventCreateWithFlags(&evWoutCv, cudaEventDisableTiming);
        cudaEventCreateWithFlags(&evM,      cudaEventDisableTiming);
    }

    const int G44  = (DD / 4) * DD / 256;
    const int G416 = (DD / 4) * DFF / 256;

    // fork s1, s2 from main stream
    cudaEventRecord(evRoot, 0);
    cudaStreamWaitEvent(s1, evRoot, 0);
    cudaStreamWaitEvent(s2, evRoot, 0);

    // s2: wo + w_out converts (consumed late; hide under GEMMs)
    convert_kernel<<<G44, 256, 0, s2>>>((const float4*)wo, (uint2*)(wt + WO_OFF));
    cudaEventRecord(evWoCv, s2);
    convert_kernel<<<G416, 256, 0, s2>>>((const float4*)w_out, (uint2*)(wt + WOUT_OFF));
    cudaEventRecord(evWoutCv, s2);

    // s1: wk + wv converts (QKV dep), then w_in convert + MLP-in GEMM
    convert_kernel<<<G44, 256, 0, s1>>>((const float4*)wk, (uint2*)(wt + WK_OFF));
    convert_kernel<<<G44, 256, 0, s1>>>((const float4*)wv, (uint2*)(wt + WV_OFF));
    cudaEventRecord(evKV, s1);
    convert_kernel<<<G416, 256, 0, s1>>>((const float4*)w_in, (uint2*)(wt + WIN_OFF));

    // main: wq convert + LN
    convert_kernel<<<G44, 256>>>((const float4*)wq, (uint2*)(wt + WQ_OFF));
    ln_kernel<<<TT, 256>>>(x, ln_s, ln_o, h);
    cudaEventRecord(evLN, 0);

    // s1: MLP-in GEMM (needs h + w_in)
    cudaStreamWaitEvent(s1, evLN, 0);
    tgemm_kernel<1, __half><<<dim3(DFF / 256, TT / 128), 256, GSMEM_TOTAL, s1>>>(h, wt + WIN_OFF, b_in, nullptr, m, DFF, DD);
    cudaEventRecord(evM, s1);

    // main: QKV (with fused RoPE) -> attention -> Wo
    cudaStreamWaitEvent(0, evKV, 0);
    tgemm_qkv_kernel<<<dim3(DD / 256, TT / 128, 3), 256, GSMEM_TOTAL>>>(h, wt, q, k, v);
    attn_kernel<<<dim3(TT / 128, HH), 256, ATTN_SMEM>>>(q, k, v, y);
    cudaStreamWaitEvent(0, evWoCv, 0);
    tgemm_kernel<2, float><<<dim3(DD / 256, TT / 128), 256, GSMEM_TOTAL>>>(y, wt + WO_OFF, nullptr, x, tmp, DD, DD);

    // join: MLP-out needs m (s1), w_out (s2), tmp (main)
    cudaStreamWaitEvent(0, evM, 0);
    cudaStreamWaitEvent(0, evWoutCv, 0);
    tgemm_kernel<3, float><<<dim3(DD / 256, TT / 128), 256, GSMEM_TOTAL>>>(m, wt + WOUT_OFF, b_out, tmp, out, DD, DFF);
}

// round 16
// speedup vs baseline: 1.1778x; 1.0114x over previous
#include <cuda_runtime.h>
#include <cuda_fp16.h>
#include <math.h>
#include <stdint.h>

// ---------------- problem constants ----------------
#define TT    2048
#define DD    4096
#define HH    16
#define DHD   256
#define DFF   16384

// ---------------- scratch (device globals; no cudaMalloc allowed) ----------------
__device__ __half g_h  [TT * DD];      // LN output
__device__ __half g_q  [TT * DD];
__device__ __half g_k  [TT * DD];
__device__ __half g_v  [TT * DD];
__device__ __half g_y  [TT * DD];      // attention output
__device__ float  g_tmp[TT * DD];
__device__ __half g_m  [TT * DFF];
__device__ float  g_rope[TT * 32 * 2]; // (cos,sin) per (t,f)
// fp16 weights in NATIVE [K,N] layout (converted, not transposed)
__device__ __half g_wt [4u*4096u*4096u + 2u*4096u*16384u];

#define WQ_OFF    0u
#define WK_OFF    16777216u
#define WV_OFF    33554432u
#define WO_OFF    50331648u
#define WIN_OFF   67108864u
#define WOUT_OFF  134217728u

// ---------------- helpers ----------------
__device__ __forceinline__ uint32_t smem_u32(const void* p) {
    uint32_t r;
    asm("{ .reg .u64 t; cvta.to.shared.u64 t, %1; cvt.u32.u64 %0, t; }" : "=r"(r) : "l"(p));
    return r;
}
__device__ __forceinline__ void cpasync16(uint32_t dst, const void* src) {
    asm volatile("cp.async.cg.shared.global [%0], [%1], 16;" :: "r"(dst), "l"(src));
}
#define CP_COMMIT() asm volatile("cp.async.commit_group;" ::: "memory")

__device__ __forceinline__ void ldsm_x4(uint32_t (&r)[4], uint32_t addr) {
    asm volatile("ldmatrix.sync.aligned.m8n8.x4.shared.b16 {%0,%1,%2,%3}, [%4];"
        : "=r"(r[0]), "=r"(r[1]), "=r"(r[2]), "=r"(r[3]) : "r"(addr));
}
__device__ __forceinline__ void ldsm_x4_trans(uint32_t (&r)[4], uint32_t addr) {
    asm volatile("ldmatrix.sync.aligned.m8n8.x4.trans.shared.b16 {%0,%1,%2,%3}, [%4];"
        : "=r"(r[0]), "=r"(r[1]), "=r"(r[2]), "=r"(r[3]) : "r"(addr));
}
__device__ __forceinline__ void mma_f16(float (&d)[4], const uint32_t (&a)[4],
                                        uint32_t b0, uint32_t b1) {
    asm volatile("mma.sync.aligned.m16n8k16.row.col.f32.f16.f16.f32 "
        "{%0,%1,%2,%3}, {%4,%5,%6,%7}, {%8,%9}, {%0,%1,%2,%3};"
        : "+f"(d[0]), "+f"(d[1]), "+f"(d[2]), "+f"(d[3])
        : "r"(a[0]), "r"(a[1]), "r"(a[2]), "r"(a[3]), "r"(b0), "r"(b1));
}
__device__ __forceinline__ uint32_t h2pack(float x, float y) {
    __half2 h = __floats2half2_rn(x, y);
    return *(uint32_t*)&h;
}

// swizzles: 128B-row tiles (A) and 512B-row tiles (B)
#define TSWZ(off)   ((off) ^ (((off) >> 3) & 0x70))
#define SWZ512(off) ((off) ^ (((off) >> 5) & 0x70))

// ---------------- LayerNorm (fp16 output) ----------------
__global__ __launch_bounds__(256) void ln_kernel(const float* __restrict__ x,
                                                 const float* __restrict__ g,
                                                 const float* __restrict__ b,
                                                 __half* __restrict__ h) {
    int row = blockIdx.x;
    const float4* xr = (const float4*)(x + (size_t)row * DD);
    float s = 0.f, s2 = 0.f;
    for (int i = threadIdx.x; i < DD / 4; i += 256) {
        float4 v = xr[i];
        s  += v.x + v.y + v.z + v.w;
        s2 += v.x*v.x + v.y*v.y + v.z*v.z + v.w*v.w;
    }
    for (int o = 16; o > 0; o >>= 1) {
        s  += __shfl_xor_sync(~0u, s,  o);
        s2 += __shfl_xor_sync(~0u, s2, o);
    }
    __shared__ float sh[16];
    int w = threadIdx.x >> 5;
    if ((threadIdx.x & 31) == 0) { sh[w] = s; sh[8 + w] = s2; }
    __syncthreads();
    if (threadIdx.x < 32) {
        float a = threadIdx.x < 8 ? sh[threadIdx.x]     : 0.f;
        float c = threadIdx.x < 8 ? sh[8 + threadIdx.x] : 0.f;
        for (int o = 4; o > 0; o >>= 1) {
            a += __shfl_xor_sync(~0u, a, o);
            c += __shfl_xor_sync(~0u, c, o);
        }
        if (threadIdx.x == 0) { sh[0] = a; sh[8] = c; }
    }
    __syncthreads();
    float mean = sh[0] * (1.f / DD);
    float var  = sh[8] * (1.f / DD) - mean * mean;
    float rstd = rsqrtf(var + 1e-6f);
    __half2* hr = (__half2*)(h + (size_t)row * DD);
    const float4* gg4 = (const float4*)g;
    const float4* bb4 = (const float4*)b;
    for (int i = threadIdx.x; i < DD / 4; i += 256) {
        float4 v = xr[i], gg = gg4[i], bb = bb4[i];
        hr[i * 2]     = __floats2half2_rn((v.x - mean) * rstd * gg.x + bb.x,
                                          (v.y - mean) * rstd * gg.y + bb.y);
        hr[i * 2 + 1] = __floats2half2_rn((v.z - mean) * rstd * gg.z + bb.z,
                                          (v.w - mean) * rstd * gg.w + bb.w);
    }
}

// ---------------- streaming fp32 -> fp16 convert (layout preserved) ----------------
__global__ __launch_bounds__(256) void convert_kernel(const float4* __restrict__ in,
                                                      uint2* __restrict__ out) {
    int i = blockIdx.x * 256 + threadIdx.x;
    float4 v = in[i];
    uint2 o;
    o.x = h2pack(v.x, v.y);
    o.y = h2pack(v.z, v.w);
    out[i] = o;
}

// ---------------- RoPE table: cos/sin(t * 10000^(-f/32)) for (t,f) ----------------
__global__ __launch_bounds__(256) void rope_table_kernel(float* __restrict__ tab) {
    int idx = blockIdx.x * 256 + threadIdx.x;   // TT*32 entries
    int f = idx & 31;
    int t = idx >> 5;
    float inv = 1.0f / powf(10000.0f, (float)f * (1.0f / 32.0f));
    float ang = (float)t * inv;
    float sn, cs;
    sincosf(ang, &sn, &cs);
    tab[idx * 2]     = cs;
    tab[idx * 2 + 1] = sn;
}

// ---------------- RoPE in-place on fp16 q, k (table lookup) ----------------
__global__ __launch_bounds__(256) void rope_kernel(__half* __restrict__ q, __half* __restrict__ k,
                                                   const float* __restrict__ tab) {
    int idx = blockIdx.x * 256 + threadIdx.x;
    int f = idx & 31;
    int hh = (idx >> 5) & (HH - 1);
    int t = idx >> 9;
    float2 cssn = *(const float2*)(tab + (size_t)(t * 32 + f) * 2);
    float cs = cssn.x, sn = cssn.y;
    size_t base = (size_t)t * DD + hh * DHD + f;
    {
        float a = __half2float(q[base]), b = __half2float(q[base + 32]);
        q[base]      = __float2half_rn(a * cs - b * sn);
        q[base + 32] = __float2half_rn(a * sn + b * cs);
    }
    {
        float a = __half2float(k[base]), b = __half2float(k[base + 32]);
        k[base]      = __float2half_rn(a * cs - b * sn);
        k[base + 32] = __float2half_rn(a * sn + b * cs);
    }
}

// ---------------- fp16 mma GEMM: CTA 128x256, warp 64x64, 4-stage cp.async (R13 body) ----------------
__device__ __forceinline__ float gelu_f(float v) {
    float t = tanhf(0.7978845608028654f * (v + 0.044715f * v * v * v));
    return 0.5f * v * (1.f + t);
}

#define STAGE_BYTES 49152            // A 16KB (128m x 128B) + B 32KB (64k x 512B)
#define B_SMEM_OFF  16384
#define GSTAGES 4
#define GSMEM_TOTAL (GSTAGES * STAGE_BYTES)   // 196608

template <int EPI, typename OutT>
__device__ __forceinline__ void tgemm_body(const __half* __restrict__ A, const __half* __restrict__ B,
                                           const float* __restrict__ bias, const float* __restrict__ res,
                                           OutT* __restrict__ C, int N, int K) {
    extern __shared__ __align__(1024) char gsm[];
    uint32_t sbase = smem_u32(gsm);
    int tid = threadIdx.x, lane = tid & 31, wid = tid >> 5;

    // column-major CTA raster (B strip shared by co-resident CTAs)
    int bid = blockIdx.y * gridDim.x + blockIdx.x;
    int by  = bid % gridDim.y;
    int bx  = bid / gridDim.y;
    int bm = by * 128, bn = bx * 256;

    int ntiles = K >> 6;
    int wm = (wid >> 2) * 64, wn = (wid & 3) * 64;

    uint32_t doffA[4]; int soffA[4];
#pragma unroll
    for (int j = 0; j < 4; ++j) {
        int idx = tid + 256 * j;
        int row = idx >> 3, seg = idx & 7;
        soffA[j] = row * K + seg * 8;
        doffA[j] = TSWZ((uint32_t)(row * 128 + seg * 16));
    }
    uint32_t doffB[8]; size_t soffB[8];
#pragma unroll
    for (int j = 0; j < 8; ++j) {
        int idx = tid + 256 * j;
        int krow = idx >> 5, seg = idx & 31;
        soffB[j] = (size_t)krow * N + seg * 8;
        doffB[j] = B_SMEM_OFF + SWZ512((uint32_t)(krow * 512 + seg * 16));
    }
    const __half* Abase = A + (size_t)bm * K;
    const __half* Bbase = B + bn;

#pragma unroll
    for (int p = 0; p < GSTAGES - 1; ++p) {
        uint32_t stb = sbase + p * STAGE_BYTES;
#pragma unroll
        for (int j = 0; j < 4; ++j) cpasync16(stb + doffA[j], Abase + soffA[j] + p * 64);
#pragma unroll
        for (int j = 0; j < 8; ++j) cpasync16(stb + doffB[j], Bbase + soffB[j] + (size_t)p * 64 * N);
        CP_COMMIT();
    }

    float acc[4][8][4];
#pragma unroll
    for (int i = 0; i < 4; ++i)
#pragma unroll
        for (int j = 0; j < 8; ++j)
#pragma unroll
            for (int e = 0; e < 4; ++e) acc[i][j][e] = 0.f;

    int dr = ((lane >> 3) & 1) * 8 + (lane & 7);
    int dk = ((lane >> 4) & 1) * 16;
    int vmI = lane >> 3, vii = lane & 7;
    int vsrow = (vmI & 1) * 8 + vii;
    int vcolb = (vmI >> 1) * 16;

    int stage = 0;
    for (int kt = 0; kt < ntiles; ++kt) {
        asm volatile("cp.async.wait_group 2;" ::: "memory");
        __syncthreads();

        int jt = kt + 3;
        if (jt < ntiles) {
            int ps = stage + 3; if (ps >= GSTAGES) ps -= GSTAGES;
            uint32_t stb = sbase + ps * STAGE_BYTES;
#pragma unroll
            for (int j = 0; j < 4; ++j) cpasync16(stb + doffA[j], Abase + soffA[j] + jt * 64);
#pragma unroll
            for (int j = 0; j < 8; ++j) cpasync16(stb + doffB[j], Bbase + soffB[j] + (size_t)jt * 64 * N);
        }
        CP_COMMIT();

        uint32_t stb = sbase + stage * STAGE_BYTES;
#pragma unroll
        for (int k16 = 0; k16 < 4; ++k16) {
            uint32_t a[4][4];
#pragma unroll
            for (int i = 0; i < 4; ++i)
                ldsm_x4(a[i], stb + TSWZ((uint32_t)((wm + i * 16 + dr) * 128) + (uint32_t)(k16 * 32 + dk)));
            uint32_t b[4][4];
#pragma unroll
            for (int jj = 0; jj < 4; ++jj) {
                uint32_t off = (uint32_t)((k16 * 16 + vsrow) * 512 + (wn + jj * 16) * 2 + vcolb);
                ldsm_x4_trans(b[jj], stb + B_SMEM_OFF + SWZ512(off));
            }
#pragma unroll
            for (int i = 0; i < 4; ++i)
#pragma unroll
                for (int jj = 0; jj < 4; ++jj) {
                    mma_f16(acc[i][2 * jj],     a[i], b[jj][0], b[jj][1]);
                    mma_f16(acc[i][2 * jj + 1], a[i], b[jj][2], b[jj][3]);
                }
        }
        if (++stage == GSTAGES) stage = 0;
    }

    int lr = lane >> 2, lc = (lane & 3) * 2;
#pragma unroll
    for (int i = 0; i < 4; ++i) {
        int r0 = bm + wm + i * 16 + lr;
        int r1 = r0 + 8;
        size_t ro0 = (size_t)r0 * N, ro1 = (size_t)r1 * N;
#pragma unroll
        for (int j = 0; j < 8; ++j) {
            int c = bn + wn + j * 8 + lc;
            float2 v0 = make_float2(acc[i][j][0], acc[i][j][1]);
            float2 v1 = make_float2(acc[i][j][2], acc[i][j][3]);
            if (EPI == 1) {
                float2 bb = *(const float2*)(bias + c);
                v0.x = gelu_f(v0.x + bb.x); v0.y = gelu_f(v0.y + bb.y);
                v1.x = gelu_f(v1.x + bb.x); v1.y = gelu_f(v1.y + bb.y);
            } else if (EPI == 2) {
                float2 ra = *(const float2*)(res + ro0 + c);
                float2 rb = *(const float2*)(res + ro1 + c);
                v0.x += ra.x; v0.y += ra.y; v1.x += rb.x; v1.y += rb.y;
            } else if (EPI == 3) {
                float2 bb = *(const float2*)(bias + c);
                float2 ra = *(const float2*)(res + ro0 + c);
                float2 rb = *(const float2*)(res + ro1 + c);
                v0.x += bb.x + ra.x; v0.y += bb.y + ra.y;
                v1.x += bb.x + rb.x; v1.y += bb.y + rb.y;
            }
            if (sizeof(OutT) == 2) {
                *(__half2*)((__half*)C + ro0 + c) = __floats2half2_rn(v0.x, v0.y);
                *(__half2*)((__half*)C + ro1 + c) = __floats2half2_rn(v1.x, v1.y);
            } else {
                *(float2*)((float*)C + ro0 + c) = v0;
                *(float2*)((float*)C + ro1 + c) = v1;
            }
        }
    }
}

template <int EPI, typename OutT>
__global__ __launch_bounds__(256, 1)
void tgemm_kernel(const __half* __restrict__ A, const __half* __restrict__ B,
                  const float* __restrict__ bias, const float* __restrict__ res,
                  OutT* __restrict__ C, int N, int K) {
    tgemm_body<EPI, OutT>(A, B, bias, res, C, N, K);
}

__global__ __launch_bounds__(256, 1)
void tgemm_qkv_kernel(const __half* __restrict__ h, const __half* __restrict__ wt,
                      __half* __restrict__ q, __half* __restrict__ k, __half* __restrict__ v) {
    const __half* B = (blockIdx.z == 0) ? (wt + WQ_OFF) : (blockIdx.z == 1) ? (wt + WK_OFF) : (wt + WV_OFF);
    __half* C       = (blockIdx.z == 0) ? q : (blockIdx.z == 1) ? k : v;
    tgemm_body<0, __half>(h, B, nullptr, nullptr, C, DD, DD);
}

// ---------------- fp16 mma flash attention: Br=128, 8 warps, Bc=64 ----------------
#define AT_ROWB    528
#define ATQ_BYTES  (128 * AT_ROWB)                 // 67584
#define ATKV_BYTES (64 * AT_ROWB)                  // 33792
#define ATTN_SMEM  (ATQ_BYTES + 4 * ATKV_BYTES)    // 202752

__device__ __forceinline__ void attn_load_q(uint32_t dstb, const __half* src, int tid) {
#pragma unroll
    for (int j = 0; j < 16; ++j) {
        int idx = tid + 256 * j;
        int row = idx >> 5, seg = idx & 31;
        cpasync16(dstb + row * AT_ROWB + seg * 16, src + (size_t)row * DD + seg * 8);
    }
}
__device__ __forceinline__ void attn_load_kv(uint32_t dstb, const __half* src, int tid) {
#pragma unroll
    for (int j = 0; j < 8; ++j) {
        int idx = tid + 256 * j;
        int row = idx >> 5, seg = idx & 31;
        cpasync16(dstb + row * AT_ROWB + seg * 16, src + (size_t)row * DD + seg * 8);
    }
}

__global__ __launch_bounds__(256, 1) void attn_kernel(const __half* __restrict__ q,
                                                      const __half* __restrict__ k,
                                                      const __half* __restrict__ v,
                                                      __half* __restrict__ y) {
    extern __shared__ __align__(1024) char asmem[];
    uint32_t sb = smem_u32(asmem);
    int tid = threadIdx.x, lane = tid & 31, wid = tid >> 5;   // 8 warps
    int qt = gridDim.x - 1 - blockIdx.x;                      // heavy tiles first
    int hh = blockIdx.y;
    size_t hoff = (size_t)hh * DHD;
    int ntk = 2 * qt + 2;

    uint32_t Qb = sb;
    uint32_t Kb[2] = { sb + ATQ_BYTES, sb + ATQ_BYTES + ATKV_BYTES };
    uint32_t Vb[2] = { sb + ATQ_BYTES + 2 * ATKV_BYTES, sb + ATQ_BYTES + 3 * ATKV_BYTES };

    const __half* qsrc = q + (size_t)(qt * 128) * DD + hoff;

    attn_load_q(Qb, qsrc, tid);
    attn_load_kv(Kb[0], k + hoff, tid);
    attn_load_kv(Vb[0], v + hoff, tid);
    CP_COMMIT();
    attn_load_kv(Kb[1], k + (size_t)64 * DD + hoff, tid);
    attn_load_kv(Vb[1], v + (size_t)64 * DD + hoff, tid);
    CP_COMMIT();

    float o[32][4];
#pragma unroll
    for (int j = 0; j < 32; ++j)
#pragma unroll
        for (int e = 0; e < 4; ++e) o[j][e] = 0.f;
    float m0 = -1e30f, m1 = -1e30f, l0 = 0.f, l1 = 0.f;

    int dr = ((lane >> 3) & 1) * 8 + (lane & 7);
    int dk = ((lane >> 4) & 1) * 16;
    int wm = wid * 16;                       // warp's 16 q-rows within 128
    int lr = lane >> 2, lc = (lane & 3) * 2;
    int vmI = lane >> 3, vii = lane & 7;
    int vsrow = (vmI & 1) * 8 + vii;
    int vcolb = (vmI >> 1) * 16;

    for (int kt = 0; kt < ntk; ++kt) {
        asm volatile("cp.async.wait_group 1;" ::: "memory");
        __syncthreads();
        uint32_t Kt = Kb[kt & 1], Vt = Vb[kt & 1];

        // fully-masked warp tile? (entire 16 rows above diagonal for this kt)
        bool active = (kt * 64 <= qt * 128 + wm + 15);
        if (active) {
            // ---- S = Q K^T : warp computes 16x64 ----
            float s[8][4];
#pragma unroll
            for (int j = 0; j < 8; ++j)
#pragma unroll
                for (int e = 0; e < 4; ++e) s[j][e] = 0.f;

#pragma unroll
            for (int k16 = 0; k16 < 16; ++k16) {
                uint32_t kb = (uint32_t)(k16 * 32 + dk);
                uint32_t a[4];
                ldsm_x4(a, Qb + (uint32_t)((wm + dr) * AT_ROWB) + kb);
#pragma unroll
                for (int jj = 0; jj < 4; ++jj) {
                    uint32_t b[4];
                    ldsm_x4(b, Kt + (uint32_t)((jj * 16 + dr) * AT_ROWB) + kb);
                    mma_f16(s[2 * jj],     a, b[0], b[2]);
                    mma_f16(s[2 * jj + 1], a, b[1], b[3]);
                }
            }

#pragma unroll
            for (int j = 0; j < 8; ++j)
#pragma unroll
                for (int e = 0; e < 4; ++e) s[j][e] *= 0.0625f;
            if (kt >= 2 * qt) {       // tiles intersecting the diagonal
                int rowg_base = qt * 128 + wm + lr;
                int colg_base = kt * 64 + lc;
#pragma unroll
                for (int j = 0; j < 8; ++j)
#pragma unroll
                    for (int e = 0; e < 4; ++e) {
                        int colg = colg_base + 8 * j + (e & 1);
                        int rowg = rowg_base + ((e >> 1) << 3);
                        if (colg > rowg) s[j][e] = -1e30f;
                    }
            }

            // ---- online softmax (rows lr, lr+8 of warp tile) ----
            float tm0 = -1e30f, tm1 = -1e30f;
#pragma unroll
            for (int j = 0; j < 8; ++j) {
                tm0 = fmaxf(tm0, fmaxf(s[j][0], s[j][1]));
                tm1 = fmaxf(tm1, fmaxf(s[j][2], s[j][3]));
            }
            tm0 = fmaxf(tm0, __shfl_xor_sync(~0u, tm0, 1));
            tm0 = fmaxf(tm0, __shfl_xor_sync(~0u, tm0, 2));
            tm1 = fmaxf(tm1, __shfl_xor_sync(~0u, tm1, 1));
            tm1 = fmaxf(tm1, __shfl_xor_sync(~0u, tm1, 2));
            float nm0 = fmaxf(m0, tm0), nm1 = fmaxf(m1, tm1);
            float al0 = __expf(m0 - nm0), al1 = __expf(m1 - nm1);
            m0 = nm0; m1 = nm1;
            float rs0 = 0.f, rs1 = 0.f;
#pragma unroll
            for (int j = 0; j < 8; ++j) {
                s[j][0] = __expf(s[j][0] - nm0);
                s[j][1] = __expf(s[j][1] - nm0);
                s[j][2] = __expf(s[j][2] - nm1);
                s[j][3] = __expf(s[j][3] - nm1);
                rs0 += s[j][0] + s[j][1];
                rs1 += s[j][2] + s[j][3];
            }
            rs0 += __shfl_xor_sync(~0u, rs0, 1); rs0 += __shfl_xor_sync(~0u, rs0, 2);
            rs1 += __shfl_xor_sync(~0u, rs1, 1); rs1 += __shfl_xor_sync(~0u, rs1, 2);
            l0 = l0 * al0 + rs0;
            l1 = l1 * al1 + rs1;
#pragma unroll
            for (int j = 0; j < 32; ++j) {
                o[j][0] *= al0; o[j][1] *= al0;
                o[j][2] *= al1; o[j][3] *= al1;
            }

            // ---- O += P V ----
#pragma unroll
            for (int t = 0; t < 4; ++t) {
                uint32_t pa[4];
                pa[0] = h2pack(s[2 * t][0],     s[2 * t][1]);
                pa[1] = h2pack(s[2 * t][2],     s[2 * t][3]);
                pa[2] = h2pack(s[2 * t + 1][0], s[2 * t + 1][1]);
                pa[3] = h2pack(s[2 * t + 1][2], s[2 * t + 1][3]);
                uint32_t vrow = (uint32_t)((16 * t + vsrow) * AT_ROWB);
#pragma unroll
                for (int np = 0; np < 16; ++np) {
                    uint32_t bb[4];
                    ldsm_x4_trans(bb, Vt + vrow + (uint32_t)(np * 32 + vcolb));
                    mma_f16(o[2 * np],     pa, bb[0], bb[1]);
                    mma_f16(o[2 * np + 1], pa, bb[2], bb[3]);
                }
            }
        }

        __syncthreads();
        int jt = kt + 2;
        if (jt < ntk) {
            attn_load_kv(Kb[kt & 1], k + (size_t)(jt * 64) * DD + hoff, tid);
            attn_load_kv(Vb[kt & 1], v + (size_t)(jt * 64) * DD + hoff, tid);
        }
        CP_COMMIT();
    }

    float inv0 = 1.f / l0, inv1 = 1.f / l1;
    size_t r0 = (size_t)(qt * 128 + wm + lr) * DD + hoff;
    size_t r1 = r0 + (size_t)8 * DD;
#pragma unroll
    for (int j = 0; j < 32; ++j) {
        *(__half2*)(y + r0 + 8 * j + lc) = __floats2half2_rn(o[j][0] * inv0, o[j][1] * inv0);
        *(__half2*)(y + r1 + 8 * j + lc) = __floats2half2_rn(o[j][2] * inv1, o[j][3] * inv1);
    }
}

// ---------------- launcher (tri-stream overlap) ----------------
extern "C" void kernel_launch(void* const* d_in, const int* in_sizes, int n_in,
                              void* d_out, int out_size) {
    const float* x     = (const float*)d_in[0];
    const float* wq    = (const float*)d_in[1];
    const float* wk    = (const float*)d_in[2];
    const float* wv    = (const float*)d_in[3];
    const float* wo    = (const float*)d_in[4];
    const float* w_in  = (const float*)d_in[5];
    const float* b_in  = (const float*)d_in[6];
    const float* w_out = (const float*)d_in[7];
    const float* b_out = (const float*)d_in[8];
    const float* ln_s  = (const float*)d_in[9];
    const float* ln_o  = (const float*)d_in[10];
    float* out = (float*)d_out;

    __half *h, *q, *k, *v, *y, *m, *wt;
    float *tmp, *rtab;
    cudaGetSymbolAddress((void**)&h,    g_h);
    cudaGetSymbolAddress((void**)&q,    g_q);
    cudaGetSymbolAddress((void**)&k,    g_k);
    cudaGetSymbolAddress((void**)&v,    g_v);
    cudaGetSymbolAddress((void**)&y,    g_y);
    cudaGetSymbolAddress((void**)&tmp,  g_tmp);
    cudaGetSymbolAddress((void**)&m,    g_m);
    cudaGetSymbolAddress((void**)&wt,   g_wt);
    cudaGetSymbolAddress((void**)&rtab, g_rope);

    cudaFuncSetAttribute(attn_kernel, cudaFuncAttributeMaxDynamicSharedMemorySize, ATTN_SMEM);
    cudaFuncSetAttribute(tgemm_qkv_kernel, cudaFuncAttributeMaxDynamicSharedMemorySize, GSMEM_TOTAL);
    cudaFuncSetAttribute(tgemm_kernel<1, __half>, cudaFuncAttributeMaxDynamicSharedMemorySize, GSMEM_TOTAL);
    cudaFuncSetAttribute(tgemm_kernel<2, float>,  cudaFuncAttributeMaxDynamicSharedMemorySize, GSMEM_TOTAL);
    cudaFuncSetAttribute(tgemm_kernel<3, float>,  cudaFuncAttributeMaxDynamicSharedMemorySize, GSMEM_TOTAL);

    // lazy one-time stream/event setup (handles only; no device allocations)
    static cudaStream_t s1 = nullptr, s2 = nullptr;
    static cudaEvent_t evRoot = nullptr, evLN = nullptr, evKV = nullptr,
                       evWoCv = nullptr, evWoutCv = nullptr, evM = nullptr, evTab = nullptr;
    if (s1 == nullptr) {
        cudaStreamCreateWithFlags(&s1, cudaStreamNonBlocking);
        cudaStreamCreateWithFlags(&s2, cudaStreamNonBlocking);
        cudaEventCreateWithFlags(&evRoot,   cudaEventDisableTiming);
        cudaEventCreateWithFlags(&evLN,     cudaEventDisableTiming);
        cudaEventCreateWithFlags(&evKV,     cudaEventDisableTiming);
        cudaEventCreateWithFlags(&evWoCv,   cudaEventDisableTiming);
        cudaEventCreateWithFlags(&evWoutCv, cudaEventDisableTiming);
        cudaEventCreateWithFlags(&evM,      cudaEventDisableTiming);
        cudaEventCreateWithFlags(&evTab,    cudaEventDisableTiming);
    }

    const int G44  = (DD / 4) * DD / 256;
    const int G416 = (DD / 4) * DFF / 256;

    // fork s1, s2 from main stream
    cudaEventRecord(evRoot, 0);
    cudaStreamWaitEvent(s1, evRoot, 0);
    cudaStreamWaitEvent(s2, evRoot, 0);

    // s2: rope table (hidden under converts), then wo + w_out converts
    rope_table_kernel<<<(TT * 32) / 256, 256, 0, s2>>>(rtab);
    cudaEventRecord(evTab, s2);
    convert_kernel<<<G44, 256, 0, s2>>>((const float4*)wo, (uint2*)(wt + WO_OFF));
    cudaEventRecord(evWoCv, s2);
    convert_kernel<<<G416, 256, 0, s2>>>((const float4*)w_out, (uint2*)(wt + WOUT_OFF));
    cudaEventRecord(evWoutCv, s2);

    // s1: wk + wv converts (QKV dep), then w_in convert + MLP-in GEMM
    convert_kernel<<<G44, 256, 0, s1>>>((const float4*)wk, (uint2*)(wt + WK_OFF));
    convert_kernel<<<G44, 256, 0, s1>>>((const float4*)wv, (uint2*)(wt + WV_OFF));
    cudaEventRecord(evKV, s1);
    convert_kernel<<<G416, 256, 0, s1>>>((const float4*)w_in, (uint2*)(wt + WIN_OFF));

    // main: wq convert + LN
    convert_kernel<<<G44, 256>>>((const float4*)wq, (uint2*)(wt + WQ_OFF));
    ln_kernel<<<TT, 256>>>(x, ln_s, ln_o, h);
    cudaEventRecord(evLN, 0);

    // s1: MLP-in GEMM (needs h + w_in)
    cudaStreamWaitEvent(s1, evLN, 0);
    tgemm_kernel<1, __half><<<dim3(DFF / 256, TT / 128), 256, GSMEM_TOTAL, s1>>>(h, wt + WIN_OFF, b_in, nullptr, m, DFF, DD);
    cudaEventRecord(evM, s1);

    // main: QKV -> RoPE (table) -> attention -> Wo
    cudaStreamWaitEvent(0, evKV, 0);
    tgemm_qkv_kernel<<<dim3(DD / 256, TT / 128, 3), 256, GSMEM_TOTAL>>>(h, wt, q, k, v);
    cudaStreamWaitEvent(0, evTab, 0);
    rope_kernel<<<(TT * HH * 32) / 256, 256>>>(q, k, rtab);
    attn_kernel<<<dim3(TT / 128, HH), 256, ATTN_SMEM>>>(q, k, v, y);
    cudaStreamWaitEvent(0, evWoCv, 0);
    tgemm_kernel<2, float><<<dim3(DD / 256, TT / 128), 256, GSMEM_TOTAL>>>(y, wt + WO_OFF, nullptr, x, tmp, DD, DD);

    // join: MLP-out needs m (s1), w_out (s2), tmp (main)
    cudaStreamWaitEvent(0, evM, 0);
    cudaStreamWaitEvent(0, evWoutCv, 0);
    tgemm_kernel<3, float><<<dim3(DD / 256, TT / 128), 256, GSMEM_TOTAL>>>(m, wt + WOUT_OFF, b_out, tmp, out, DD, DFF);
}

// round 17
// speedup vs baseline: 1.2017x; 1.0203x over previous
#include <cuda_runtime.h>
#include <cuda_fp16.h>
#include <math.h>
#include <stdint.h>

// ---------------- problem constants ----------------
#define TT    2048
#define DD    4096
#define HH    16
#define DHD   256
#define DFF   16384
#define KSPLIT 4096
#define NSPLITS 4

// ---------------- scratch (device globals; no cudaMalloc allowed) ----------------
__device__ __half g_h  [TT * DD];      // LN output
__device__ __half g_q  [TT * DD];
__device__ __half g_k  [TT * DD];
__device__ __half g_v  [TT * DD];
__device__ __half g_y  [TT * DD];      // attention output
__device__ float  g_tmp[TT * DD];
__device__ __half g_m  [TT * DFF];
__device__ float  g_rope[TT * 32 * 2]; // (cos,sin) per (t,f)
__device__ float  g_part[(size_t)NSPLITS * TT * DD];  // split-K partials for MLP-out
// fp16 weights in NATIVE [K,N] layout (converted, not transposed)
__device__ __half g_wt [4u*4096u*4096u + 2u*4096u*16384u];

#define WQ_OFF    0u
#define WK_OFF    16777216u
#define WV_OFF    33554432u
#define WO_OFF    50331648u
#define WIN_OFF   67108864u
#define WOUT_OFF  134217728u

// ---------------- helpers ----------------
__device__ __forceinline__ uint32_t smem_u32(const void* p) {
    uint32_t r;
    asm("{ .reg .u64 t; cvta.to.shared.u64 t, %1; cvt.u32.u64 %0, t; }" : "=r"(r) : "l"(p));
    return r;
}
__device__ __forceinline__ void cpasync16(uint32_t dst, const void* src) {
    asm volatile("cp.async.cg.shared.global [%0], [%1], 16;" :: "r"(dst), "l"(src));
}
#define CP_COMMIT() asm volatile("cp.async.commit_group;" ::: "memory")

__device__ __forceinline__ void ldsm_x4(uint32_t (&r)[4], uint32_t addr) {
    asm volatile("ldmatrix.sync.aligned.m8n8.x4.shared.b16 {%0,%1,%2,%3}, [%4];"
        : "=r"(r[0]), "=r"(r[1]), "=r"(r[2]), "=r"(r[3]) : "r"(addr));
}
__device__ __forceinline__ void ldsm_x4_trans(uint32_t (&r)[4], uint32_t addr) {
    asm volatile("ldmatrix.sync.aligned.m8n8.x4.trans.shared.b16 {%0,%1,%2,%3}, [%4];"
        : "=r"(r[0]), "=r"(r[1]), "=r"(r[2]), "=r"(r[3]) : "r"(addr));
}
__device__ __forceinline__ void mma_f16(float (&d)[4], const uint32_t (&a)[4],
                                        uint32_t b0, uint32_t b1) {
    asm volatile("mma.sync.aligned.m16n8k16.row.col.f32.f16.f16.f32 "
        "{%0,%1,%2,%3}, {%4,%5,%6,%7}, {%8,%9}, {%0,%1,%2,%3};"
        : "+f"(d[0]), "+f"(d[1]), "+f"(d[2]), "+f"(d[3])
        : "r"(a[0]), "r"(a[1]), "r"(a[2]), "r"(a[3]), "r"(b0), "r"(b1));
}
__device__ __forceinline__ uint32_t h2pack(float x, float y) {
    __half2 h = __floats2half2_rn(x, y);
    return *(uint32_t*)&h;
}

// swizzles: 128B-row tiles (A) and 512B-row tiles (B)
#define TSWZ(off)   ((off) ^ (((off) >> 3) & 0x70))
#define SWZ512(off) ((off) ^ (((off) >> 5) & 0x70))

// ---------------- LayerNorm (fp16 output) ----------------
__global__ __launch_bounds__(256) void ln_kernel(const float* __restrict__ x,
                                                 const float* __restrict__ g,
                                                 const float* __restrict__ b,
                                                 __half* __restrict__ h) {
    int row = blockIdx.x;
    const float4* xr = (const float4*)(x + (size_t)row * DD);
    float s = 0.f, s2 = 0.f;
    for (int i = threadIdx.x; i < DD / 4; i += 256) {
        float4 v = xr[i];
        s  += v.x + v.y + v.z + v.w;
        s2 += v.x*v.x + v.y*v.y + v.z*v.z + v.w*v.w;
    }
    for (int o = 16; o > 0; o >>= 1) {
        s  += __shfl_xor_sync(~0u, s,  o);
        s2 += __shfl_xor_sync(~0u, s2, o);
    }
    __shared__ float sh[16];
    int w = threadIdx.x >> 5;
    if ((threadIdx.x & 31) == 0) { sh[w] = s; sh[8 + w] = s2; }
    __syncthreads();
    if (threadIdx.x < 32) {
        float a = threadIdx.x < 8 ? sh[threadIdx.x]     : 0.f;
        float c = threadIdx.x < 8 ? sh[8 + threadIdx.x] : 0.f;
        for (int o = 4; o > 0; o >>= 1) {
            a += __shfl_xor_sync(~0u, a, o);
            c += __shfl_xor_sync(~0u, c, o);
        }
        if (threadIdx.x == 0) { sh[0] = a; sh[8] = c; }
    }
    __syncthreads();
    float mean = sh[0] * (1.f / DD);
    float var  = sh[8] * (1.f / DD) - mean * mean;
    float rstd = rsqrtf(var + 1e-6f);
    __half2* hr = (__half2*)(h + (size_t)row * DD);
    const float4* gg4 = (const float4*)g;
    const float4* bb4 = (const float4*)b;
    for (int i = threadIdx.x; i < DD / 4; i += 256) {
        float4 v = xr[i], gg = gg4[i], bb = bb4[i];
        hr[i * 2]     = __floats2half2_rn((v.x - mean) * rstd * gg.x + bb.x,
                                          (v.y - mean) * rstd * gg.y + bb.y);
        hr[i * 2 + 1] = __floats2half2_rn((v.z - mean) * rstd * gg.z + bb.z,
                                          (v.w - mean) * rstd * gg.w + bb.w);
    }
}

// ---------------- streaming fp32 -> fp16 convert (layout preserved) ----------------
__global__ __launch_bounds__(256) void convert_kernel(const float4* __restrict__ in,
                                                      uint2* __restrict__ out) {
    int i = blockIdx.x * 256 + threadIdx.x;
    float4 v = in[i];
    uint2 o;
    o.x = h2pack(v.x, v.y);
    o.y = h2pack(v.z, v.w);
    out[i] = o;
}

// ---------------- RoPE table: cos/sin(t * 10000^(-f/32)) for (t,f) ----------------
__global__ __launch_bounds__(256) void rope_table_kernel(float* __restrict__ tab) {
    int idx = blockIdx.x * 256 + threadIdx.x;   // TT*32 entries
    int f = idx & 31;
    int t = idx >> 5;
    float inv = 1.0f / powf(10000.0f, (float)f * (1.0f / 32.0f));
    float ang = (float)t * inv;
    float sn, cs;
    sincosf(ang, &sn, &cs);
    tab[idx * 2]     = cs;
    tab[idx * 2 + 1] = sn;
}

// ---------------- RoPE in-place on fp16 q, k (table lookup) ----------------
__global__ __launch_bounds__(256) void rope_kernel(__half* __restrict__ q, __half* __restrict__ k,
                                                   const float* __restrict__ tab) {
    int idx = blockIdx.x * 256 + threadIdx.x;
    int f = idx & 31;
    int hh = (idx >> 5) & (HH - 1);
    int t = idx >> 9;
    float2 cssn = *(const float2*)(tab + (size_t)(t * 32 + f) * 2);
    float cs = cssn.x, sn = cssn.y;
    size_t base = (size_t)t * DD + hh * DHD + f;
    {
        float a = __half2float(q[base]), b = __half2float(q[base + 32]);
        q[base]      = __float2half_rn(a * cs - b * sn);
        q[base + 32] = __float2half_rn(a * sn + b * cs);
    }
    {
        float a = __half2float(k[base]), b = __half2float(k[base + 32]);
        k[base]      = __float2half_rn(a * cs - b * sn);
        k[base + 32] = __float2half_rn(a * sn + b * cs);
    }
}

// ---------------- fp16 mma GEMM: CTA 128x256, warp 64x64, 4-stage cp.async (R13 body + lda) ----------------
__device__ __forceinline__ float gelu_f(float v) {
    float t = tanhf(0.7978845608028654f * (v + 0.044715f * v * v * v));
    return 0.5f * v * (1.f + t);
}

#define STAGE_BYTES 49152            // A 16KB (128m x 128B) + B 32KB (64k x 512B)
#define B_SMEM_OFF  16384
#define GSTAGES 4
#define GSMEM_TOTAL (GSTAGES * STAGE_BYTES)   // 196608

template <int EPI, typename OutT>
__device__ __forceinline__ void tgemm_body(const __half* __restrict__ A, const __half* __restrict__ B,
                                           const float* __restrict__ bias, const float* __restrict__ res,
                                           OutT* __restrict__ C, int N, int K, int lda) {
    extern __shared__ __align__(1024) char gsm[];
    uint32_t sbase = smem_u32(gsm);
    int tid = threadIdx.x, lane = tid & 31, wid = tid >> 5;

    // column-major CTA raster (B strip shared by co-resident CTAs)
    int bid = blockIdx.y * gridDim.x + blockIdx.x;
    int by  = bid % gridDim.y;
    int bx  = bid / gridDim.y;
    int bm = by * 128, bn = bx * 256;

    int ntiles = K >> 6;
    int wm = (wid >> 2) * 64, wn = (wid & 3) * 64;

    uint32_t doffA[4]; int soffA[4];
#pragma unroll
    for (int j = 0; j < 4; ++j) {
        int idx = tid + 256 * j;
        int row = idx >> 3, seg = idx & 7;
        soffA[j] = row * lda + seg * 8;
        doffA[j] = TSWZ((uint32_t)(row * 128 + seg * 16));
    }
    uint32_t doffB[8]; size_t soffB[8];
#pragma unroll
    for (int j = 0; j < 8; ++j) {
        int idx = tid + 256 * j;
        int krow = idx >> 5, seg = idx & 31;
        soffB[j] = (size_t)krow * N + seg * 8;
        doffB[j] = B_SMEM_OFF + SWZ512((uint32_t)(krow * 512 + seg * 16));
    }
    const __half* Abase = A + (size_t)bm * lda;
    const __half* Bbase = B + bn;

#pragma unroll
    for (int p = 0; p < GSTAGES - 1; ++p) {
        uint32_t stb = sbase + p * STAGE_BYTES;
#pragma unroll
        for (int j = 0; j < 4; ++j) cpasync16(stb + doffA[j], Abase + soffA[j] + p * 64);
#pragma unroll
        for (int j = 0; j < 8; ++j) cpasync16(stb + doffB[j], Bbase + soffB[j] + (size_t)p * 64 * N);
        CP_COMMIT();
    }

    float acc[4][8][4];
#pragma unroll
    for (int i = 0; i < 4; ++i)
#pragma unroll
        for (int j = 0; j < 8; ++j)
#pragma unroll
            for (int e = 0; e < 4; ++e) acc[i][j][e] = 0.f;

    int dr = ((lane >> 3) & 1) * 8 + (lane & 7);
    int dk = ((lane >> 4) & 1) * 16;
    int vmI = lane >> 3, vii = lane & 7;
    int vsrow = (vmI & 1) * 8 + vii;
    int vcolb = (vmI >> 1) * 16;

    int stage = 0;
    for (int kt = 0; kt < ntiles; ++kt) {
        asm volatile("cp.async.wait_group 2;" ::: "memory");
        __syncthreads();

        int jt = kt + 3;
        if (jt < ntiles) {
            int ps = stage + 3; if (ps >= GSTAGES) ps -= GSTAGES;
            uint32_t stb = sbase + ps * STAGE_BYTES;
#pragma unroll
            for (int j = 0; j < 4; ++j) cpasync16(stb + doffA[j], Abase + soffA[j] + jt * 64);
#pragma unroll
            for (int j = 0; j < 8; ++j) cpasync16(stb + doffB[j], Bbase + soffB[j] + (size_t)jt * 64 * N);
        }
        CP_COMMIT();

        uint32_t stb = sbase + stage * STAGE_BYTES;
#pragma unroll
        for (int k16 = 0; k16 < 4; ++k16) {
            uint32_t a[4][4];
#pragma unroll
            for (int i = 0; i < 4; ++i)
                ldsm_x4(a[i], stb + TSWZ((uint32_t)((wm + i * 16 + dr) * 128) + (uint32_t)(k16 * 32 + dk)));
            uint32_t b[4][4];
#pragma unroll
            for (int jj = 0; jj < 4; ++jj) {
                uint32_t off = (uint32_t)((k16 * 16 + vsrow) * 512 + (wn + jj * 16) * 2 + vcolb);
                ldsm_x4_trans(b[jj], stb + B_SMEM_OFF + SWZ512(off));
            }
#pragma unroll
            for (int i = 0; i < 4; ++i)
#pragma unroll
                for (int jj = 0; jj < 4; ++jj) {
                    mma_f16(acc[i][2 * jj],     a[i], b[jj][0], b[jj][1]);
                    mma_f16(acc[i][2 * jj + 1], a[i], b[jj][2], b[jj][3]);
                }
        }
        if (++stage == GSTAGES) stage = 0;
    }

    int lr = lane >> 2, lc = (lane & 3) * 2;
#pragma unroll
    for (int i = 0; i < 4; ++i) {
        int r0 = bm + wm + i * 16 + lr;
        int r1 = r0 + 8;
        size_t ro0 = (size_t)r0 * N, ro1 = (size_t)r1 * N;
#pragma unroll
        for (int j = 0; j < 8; ++j) {
            int c = bn + wn + j * 8 + lc;
            float2 v0 = make_float2(acc[i][j][0], acc[i][j][1]);
            float2 v1 = make_float2(acc[i][j][2], acc[i][j][3]);
            if (EPI == 1) {
                float2 bb = *(const float2*)(bias + c);
                v0.x = gelu_f(v0.x + bb.x); v0.y = gelu_f(v0.y + bb.y);
                v1.x = gelu_f(v1.x + bb.x); v1.y = gelu_f(v1.y + bb.y);
            } else if (EPI == 2) {
                float2 ra = *(const float2*)(res + ro0 + c);
                float2 rb = *(const float2*)(res + ro1 + c);
                v0.x += ra.x; v0.y += ra.y; v1.x += rb.x; v1.y += rb.y;
            } else if (EPI == 3) {
                float2 bb = *(const float2*)(bias + c);
                float2 ra = *(const float2*)(res + ro0 + c);
                float2 rb = *(const float2*)(res + ro1 + c);
                v0.x += bb.x + ra.x; v0.y += bb.y + ra.y;
                v1.x += bb.x + rb.x; v1.y += bb.y + rb.y;
            }
            if (sizeof(OutT) == 2) {
                *(__half2*)((__half*)C + ro0 + c) = __floats2half2_rn(v0.x, v0.y);
                *(__half2*)((__half*)C + ro1 + c) = __floats2half2_rn(v1.x, v1.y);
            } else {
                *(float2*)((float*)C + ro0 + c) = v0;
                *(float2*)((float*)C + ro1 + c) = v1;
            }
        }
    }
}

template <int EPI, typename OutT>
__global__ __launch_bounds__(256, 1)
void tgemm_kernel(const __half* __restrict__ A, const __half* __restrict__ B,
                  const float* __restrict__ bias, const float* __restrict__ res,
                  OutT* __restrict__ C, int N, int K) {
    tgemm_body<EPI, OutT>(A, B, bias, res, C, N, K, K);
}

__global__ __launch_bounds__(256, 1)
void tgemm_qkv_kernel(const __half* __restrict__ h, const __half* __restrict__ wt,
                      __half* __restrict__ q, __half* __restrict__ k, __half* __restrict__ v) {
    const __half* B = (blockIdx.z == 0) ? (wt + WQ_OFF) : (blockIdx.z == 1) ? (wt + WK_OFF) : (wt + WV_OFF);
    __half* C       = (blockIdx.z == 0) ? q : (blockIdx.z == 1) ? k : v;
    tgemm_body<0, __half>(h, B, nullptr, nullptr, C, DD, DD, DD);
}

// split-K MLP-out: z-slice s computes A[:, s*4096:(s+1)*4096] @ B[s*4096:..., :] -> partials
__global__ __launch_bounds__(256, 1)
void tgemm_splitk_kernel(const __half* __restrict__ A, const __half* __restrict__ B,
                         float* __restrict__ part) {
    int s = blockIdx.z;
    tgemm_body<0, float>(A + s * KSPLIT, B + (size_t)s * KSPLIT * DD, nullptr, nullptr,
                         part + (size_t)s * TT * DD, DD, KSPLIT, DFF);
}

// out = sum(partials) + b_out[col] + tmp
__global__ __launch_bounds__(256) void splitk_reduce_kernel(const float4* __restrict__ part,
                                                            const float* __restrict__ bias,
                                                            const float4* __restrict__ tmp,
                                                            float4* __restrict__ out) {
    int i = blockIdx.x * 256 + threadIdx.x;        // TT*DD/4 float4s
    const size_t S = (size_t)TT * DD / 4;
    float4 a = part[i];
    float4 b = part[i + S];
    float4 c = part[i + 2 * S];
    float4 d = part[i + 3 * S];
    float4 t = tmp[i];
    const float4 bb = *(const float4*)(bias + (i & (DD / 4 - 1)) * 4);
    float4 o;
    o.x = a.x + b.x + c.x + d.x + bb.x + t.x;
    o.y = a.y + b.y + c.y + d.y + bb.y + t.y;
    o.z = a.z + b.z + c.z + d.z + bb.z + t.z;
    o.w = a.w + b.w + c.w + d.w + bb.w + t.w;
    out[i] = o;
}

// ---------------- fp16 mma flash attention: Br=128, 8 warps, Bc=64 ----------------
#define AT_ROWB    528
#define ATQ_BYTES  (128 * AT_ROWB)                 // 67584
#define ATKV_BYTES (64 * AT_ROWB)                  // 33792
#define ATTN_SMEM  (ATQ_BYTES + 4 * ATKV_BYTES)    // 202752

__device__ __forceinline__ void attn_load_q(uint32_t dstb, const __half* src, int tid) {
#pragma unroll
    for (int j = 0; j < 16; ++j) {
        int idx = tid + 256 * j;
        int row = idx >> 5, seg = idx & 31;
        cpasync16(dstb + row * AT_ROWB + seg * 16, src + (size_t)row * DD + seg * 8);
    }
}
__device__ __forceinline__ void attn_load_kv(uint32_t dstb, const __half* src, int tid) {
#pragma unroll
    for (int j = 0; j < 8; ++j) {
        int idx = tid + 256 * j;
        int row = idx >> 5, seg = idx & 31;
        cpasync16(dstb + row * AT_ROWB + seg * 16, src + (size_t)row * DD + seg * 8);
    }
}

__global__ __launch_bounds__(256, 1) void attn_kernel(const __half* __restrict__ q,
                                                      const __half* __restrict__ k,
                                                      const __half* __restrict__ v,
                                                      __half* __restrict__ y) {
    extern __shared__ __align__(1024) char asmem[];
    uint32_t sb = smem_u32(asmem);
    int tid = threadIdx.x, lane = tid & 31, wid = tid >> 5;   // 8 warps
    int qt = gridDim.x - 1 - blockIdx.x;                      // heavy tiles first
    int hh = blockIdx.y;
    size_t hoff = (size_t)hh * DHD;
    int ntk = 2 * qt + 2;

    uint32_t Qb = sb;
    uint32_t Kb[2] = { sb + ATQ_BYTES, sb + ATQ_BYTES + ATKV_BYTES };
    uint32_t Vb[2] = { sb + ATQ_BYTES + 2 * ATKV_BYTES, sb + ATQ_BYTES + 3 * ATKV_BYTES };

    const __half* qsrc = q + (size_t)(qt * 128) * DD + hoff;

    attn_load_q(Qb, qsrc, tid);
    attn_load_kv(Kb[0], k + hoff, tid);
    attn_load_kv(Vb[0], v + hoff, tid);
    CP_COMMIT();
    attn_load_kv(Kb[1], k + (size_t)64 * DD + hoff, tid);
    attn_load_kv(Vb[1], v + (size_t)64 * DD + hoff, tid);
    CP_COMMIT();

    float o[32][4];
#pragma unroll
    for (int j = 0; j < 32; ++j)
#pragma unroll
        for (int e = 0; e < 4; ++e) o[j][e] = 0.f;
    float m0 = -1e30f, m1 = -1e30f, l0 = 0.f, l1 = 0.f;

    int dr = ((lane >> 3) & 1) * 8 + (lane & 7);
    int dk = ((lane >> 4) & 1) * 16;
    int wm = wid * 16;                       // warp's 16 q-rows within 128
    int lr = lane >> 2, lc = (lane & 3) * 2;
    int vmI = lane >> 3, vii = lane & 7;
    int vsrow = (vmI & 1) * 8 + vii;
    int vcolb = (vmI >> 1) * 16;

    for (int kt = 0; kt < ntk; ++kt) {
        asm volatile("cp.async.wait_group 1;" ::: "memory");
        __syncthreads();
        uint32_t Kt = Kb[kt & 1], Vt = Vb[kt & 1];

        // fully-masked warp tile? (entire 16 rows above diagonal for this kt)
        bool active = (kt * 64 <= qt * 128 + wm + 15);
        if (active) {
            // ---- S = Q K^T : warp computes 16x64 ----
            float s[8][4];
#pragma unroll
            for (int j = 0; j < 8; ++j)
#pragma unroll
                for (int e = 0; e < 4; ++e) s[j][e] = 0.f;

#pragma unroll
            for (int k16 = 0; k16 < 16; ++k16) {
                uint32_t kb = (uint32_t)(k16 * 32 + dk);
                uint32_t a[4];
                ldsm_x4(a, Qb + (uint32_t)((wm + dr) * AT_ROWB) + kb);
#pragma unroll
                for (int jj = 0; jj < 4; ++jj) {
                    uint32_t b[4];
                    ldsm_x4(b, Kt + (uint32_t)((jj * 16 + dr) * AT_ROWB) + kb);
                    mma_f16(s[2 * jj],     a, b[0], b[2]);
                    mma_f16(s[2 * jj + 1], a, b[1], b[3]);
                }
            }

#pragma unroll
            for (int j = 0; j < 8; ++j)
#pragma unroll
                for (int e = 0; e < 4; ++e) s[j][e] *= 0.0625f;
            if (kt >= 2 * qt) {       // tiles intersecting the diagonal
                int rowg_base = qt * 128 + wm + lr;
                int colg_base = kt * 64 + lc;
#pragma unroll
                for (int j = 0; j < 8; ++j)
#pragma unroll
                    for (int e = 0; e < 4; ++e) {
                        int colg = colg_base + 8 * j + (e & 1);
                        int rowg = rowg_base + ((e >> 1) << 3);
                        if (colg > rowg) s[j][e] = -1e30f;
                    }
            }

            // ---- online softmax (rows lr, lr+8 of warp tile) ----
            float tm0 = -1e30f, tm1 = -1e30f;
#pragma unroll
            for (int j = 0; j < 8; ++j) {
                tm0 = fmaxf(tm0, fmaxf(s[j][0], s[j][1]));
                tm1 = fmaxf(tm1, fmaxf(s[j][2], s[j][3]));
            }
            tm0 = fmaxf(tm0, __shfl_xor_sync(~0u, tm0, 1));
            tm0 = fmaxf(tm0, __shfl_xor_sync(~0u, tm0, 2));
            tm1 = fmaxf(tm1, __shfl_xor_sync(~0u, tm1, 1));
            tm1 = fmaxf(tm1, __shfl_xor_sync(~0u, tm1, 2));
            float nm0 = fmaxf(m0, tm0), nm1 = fmaxf(m1, tm1);
            float al0 = __expf(m0 - nm0), al1 = __expf(m1 - nm1);
            m0 = nm0; m1 = nm1;
            float rs0 = 0.f, rs1 = 0.f;
#pragma unroll
            for (int j = 0; j < 8; ++j) {
                s[j][0] = __expf(s[j][0] - nm0);
                s[j][1] = __expf(s[j][1] - nm0);
                s[j][2] = __expf(s[j][2] - nm1);
                s[j][3] = __expf(s[j][3] - nm1);
                rs0 += s[j][0] + s[j][1];
                rs1 += s[j][2] + s[j][3];
            }
            rs0 += __shfl_xor_sync(~0u, rs0, 1); rs0 += __shfl_xor_sync(~0u, rs0, 2);
            rs1 += __shfl_xor_sync(~0u, rs1, 1); rs1 += __shfl_xor_sync(~0u, rs1, 2);
            l0 = l0 * al0 + rs0;
            l1 = l1 * al1 + rs1;
#pragma unroll
            for (int j = 0; j < 32; ++j) {
                o[j][0] *= al0; o[j][1] *= al0;
                o[j][2] *= al1; o[j][3] *= al1;
            }

            // ---- O += P V ----
#pragma unroll
            for (int t = 0; t < 4; ++t) {
                uint32_t pa[4];
                pa[0] = h2pack(s[2 * t][0],     s[2 * t][1]);
                pa[1] = h2pack(s[2 * t][2],     s[2 * t][3]);
                pa[2] = h2pack(s[2 * t + 1][0], s[2 * t + 1][1]);
                pa[3] = h2pack(s[2 * t + 1][2], s[2 * t + 1][3]);
                uint32_t vrow = (uint32_t)((16 * t + vsrow) * AT_ROWB);
#pragma unroll
                for (int np = 0; np < 16; ++np) {
                    uint32_t bb[4];
                    ldsm_x4_trans(bb, Vt + vrow + (uint32_t)(np * 32 + vcolb));
                    mma_f16(o[2 * np],     pa, bb[0], bb[1]);
                    mma_f16(o[2 * np + 1], pa, bb[2], bb[3]);
                }
            }
        }

        __syncthreads();
        int jt = kt + 2;
        if (jt < ntk) {
            attn_load_kv(Kb[kt & 1], k + (size_t)(jt * 64) * DD + hoff, tid);
            attn_load_kv(Vb[kt & 1], v + (size_t)(jt * 64) * DD + hoff, tid);
        }
        CP_COMMIT();
    }

    float inv0 = 1.f / l0, inv1 = 1.f / l1;
    size_t r0 = (size_t)(qt * 128 + wm + lr) * DD + hoff;
    size_t r1 = r0 + (size_t)8 * DD;
#pragma unroll
    for (int j = 0; j < 32; ++j) {
        *(__half2*)(y + r0 + 8 * j + lc) = __floats2half2_rn(o[j][0] * inv0, o[j][1] * inv0);
        *(__half2*)(y + r1 + 8 * j + lc) = __floats2half2_rn(o[j][2] * inv1, o[j][3] * inv1);
    }
}

// ---------------- launcher (tri-stream overlap) ----------------
extern "C" void kernel_launch(void* const* d_in, const int* in_sizes, int n_in,
                              void* d_out, int out_size) {
    const float* x     = (const float*)d_in[0];
    const float* wq    = (const float*)d_in[1];
    const float* wk    = (const float*)d_in[2];
    const float* wv    = (const float*)d_in[3];
    const float* wo    = (const float*)d_in[4];
    const float* w_in  = (const float*)d_in[5];
    const float* b_in  = (const float*)d_in[6];
    const float* w_out = (const float*)d_in[7];
    const float* b_out = (const float*)d_in[8];
    const float* ln_s  = (const float*)d_in[9];
    const float* ln_o  = (const float*)d_in[10];
    float* out = (float*)d_out;

    __half *h, *q, *k, *v, *y, *m, *wt;
    float *tmp, *rtab, *part;
    cudaGetSymbolAddress((void**)&h,    g_h);
    cudaGetSymbolAddress((void**)&q,    g_q);
    cudaGetSymbolAddress((void**)&k,    g_k);
    cudaGetSymbolAddress((void**)&v,    g_v);
    cudaGetSymbolAddress((void**)&y,    g_y);
    cudaGetSymbolAddress((void**)&tmp,  g_tmp);
    cudaGetSymbolAddress((void**)&m,    g_m);
    cudaGetSymbolAddress((void**)&wt,   g_wt);
    cudaGetSymbolAddress((void**)&rtab, g_rope);
    cudaGetSymbolAddress((void**)&part, g_part);

    cudaFuncSetAttribute(attn_kernel, cudaFuncAttributeMaxDynamicSharedMemorySize, ATTN_SMEM);
    cudaFuncSetAttribute(tgemm_qkv_kernel, cudaFuncAttributeMaxDynamicSharedMemorySize, GSMEM_TOTAL);
    cudaFuncSetAttribute(tgemm_kernel<1, __half>, cudaFuncAttributeMaxDynamicSharedMemorySize, GSMEM_TOTAL);
    cudaFuncSetAttribute(tgemm_kernel<2, float>,  cudaFuncAttributeMaxDynamicSharedMemorySize, GSMEM_TOTAL);
    cudaFuncSetAttribute(tgemm_splitk_kernel,     cudaFuncAttributeMaxDynamicSharedMemorySize, GSMEM_TOTAL);

    // lazy one-time stream/event setup (handles only; no device allocations)
    static cudaStream_t s1 = nullptr, s2 = nullptr;
    static cudaEvent_t evRoot = nullptr, evLN = nullptr, evKV = nullptr,
                       evWoCv = nullptr, evWoutCv = nullptr, evM = nullptr, evTab = nullptr;
    if (s1 == nullptr) {
        cudaStreamCreateWithFlags(&s1, cudaStreamNonBlocking);
        cudaStreamCreateWithFlags(&s2, cudaStreamNonBlocking);
        cudaEventCreateWithFlags(&evRoot,   cudaEventDisableTiming);
        cudaEventCreateWithFlags(&evLN,     cudaEventDisableTiming);
        cudaEventCreateWithFlags(&evKV,     cudaEventDisableTiming);
        cudaEventCreateWithFlags(&evWoCv,   cudaEventDisableTiming);
        cudaEventCreateWithFlags(&evWoutCv, cudaEventDisableTiming);
        cudaEventCreateWithFlags(&evM,      cudaEventDisableTiming);
        cudaEventCreateWithFlags(&evTab,    cudaEventDisableTiming);
    }

    const int G44  = (DD / 4) * DD / 256;
    const int G416 = (DD / 4) * DFF / 256;

    // fork s1, s2 from main stream
    cudaEventRecord(evRoot, 0);
    cudaStreamWaitEvent(s1, evRoot, 0);
    cudaStreamWaitEvent(s2, evRoot, 0);

    // s2: rope table (hidden under converts), then wo + w_out converts
    rope_table_kernel<<<(TT * 32) / 256, 256, 0, s2>>>(rtab);
    cudaEventRecord(evTab, s2);
    convert_kernel<<<G44, 256, 0, s2>>>((const float4*)wo, (uint2*)(wt + WO_OFF));
    cudaEventRecord(evWoCv, s2);
    convert_kernel<<<G416, 256, 0, s2>>>((const float4*)w_out, (uint2*)(wt + WOUT_OFF));
    cudaEventRecord(evWoutCv, s2);

    // s1: wk + wv converts (QKV dep), then w_in convert + MLP-in GEMM
    convert_kernel<<<G44, 256, 0, s1>>>((const float4*)wk, (uint2*)(wt + WK_OFF));
    convert_kernel<<<G44, 256, 0, s1>>>((const float4*)wv, (uint2*)(wt + WV_OFF));
    cudaEventRecord(evKV, s1);
    convert_kernel<<<G416, 256, 0, s1>>>((const float4*)w_in, (uint2*)(wt + WIN_OFF));

    // main: wq convert + LN
    convert_kernel<<<G44, 256>>>((const float4*)wq, (uint2*)(wt + WQ_OFF));
    ln_kernel<<<TT, 256>>>(x, ln_s, ln_o, h);
    cudaEventRecord(evLN, 0);

    // s1: MLP-in GEMM (needs h + w_in)
    cudaStreamWaitEvent(s1, evLN, 0);
    tgemm_kernel<1, __half><<<dim3(DFF / 256, TT / 128), 256, GSMEM_TOTAL, s1>>>(h, wt + WIN_OFF, b_in, nullptr, m, DFF, DD);
    cudaEventRecord(evM, s1);

    // main: QKV -> RoPE (table) -> attention -> Wo
    cudaStreamWaitEvent(0, evKV, 0);
    tgemm_qkv_kernel<<<dim3(DD / 256, TT / 128, 3), 256, GSMEM_TOTAL>>>(h, wt, q, k, v);
    cudaStreamWaitEvent(0, evTab, 0);
    rope_kernel<<<(TT * HH * 32) / 256, 256>>>(q, k, rtab);
    attn_kernel<<<dim3(TT / 128, HH), 256, ATTN_SMEM>>>(q, k, v, y);
    cudaStreamWaitEvent(0, evWoCv, 0);
    tgemm_kernel<2, float><<<dim3(DD / 256, TT / 128), 256, GSMEM_TOTAL>>>(y, wt + WO_OFF, nullptr, x, tmp, DD, DD);

    // join: MLP-out (split-K=4) needs m (s1), w_out (s2), tmp (main)
    cudaStreamWaitEvent(0, evM, 0);
    cudaStreamWaitEvent(0, evWoutCv, 0);
    tgemm_splitk_kernel<<<dim3(DD / 256, TT / 128, NSPLITS), 256, GSMEM_TOTAL>>>(m, wt + WOUT_OFF, part);
    splitk_reduce_kernel<<<(TT * DD / 4) / 256, 256>>>((const float4*)part, b_out, (const float4*)tmp, (float4*)out);
}